// round 7
// baseline (speedup 1.0000x reference)
#include <cuda_runtime.h>
#include <cuda_bf16.h>
#include <math.h>
#include <stdint.h>

#define NN 50000
#define EE 100000
#define HH 768
#define NHD 12
#define HDD 64
#define NGR 64
#define NCL 10
#define H2 384

// ---------------- scratch (static device globals; no allocation) ----------------
__device__ float g_bufA[(size_t)NN * HH];
__device__ float g_bufB[(size_t)NN * HH];
__device__ __nv_bfloat16 g_Ah[(size_t)NN * HH];
__device__ __nv_bfloat16 g_Al[(size_t)NN * HH];
__device__ __nv_bfloat16 g_Wh[(size_t)HH * HH];   // transposed: [N=768][K=768]
__device__ __nv_bfloat16 g_Wl[(size_t)HH * HH];
__device__ float g_dinv[NN];
__device__ int   g_cnt[NN];
__device__ int   g_rowstart[NN + 1];
__device__ int   g_cursor[NN];
__device__ int   g_csrsrc[EE];
__device__ float g_as[NN * NHD];
__device__ float g_ad[NN * NHD];
__device__ float g_pool[NGR * HH];
__device__ float g_zmlp[NGR * H2];

__device__ __forceinline__ float lrelu(float x) { return x > 0.f ? x : 0.2f * x; }

// ---------------- CSR build ----------------
__global__ void k_zero_cnt() {
    int i = blockIdx.x * blockDim.x + threadIdx.x;
    if (i < NN) g_cnt[i] = 0;
}

__global__ void k_count(const int* __restrict__ ei) {
    int e = blockIdx.x * blockDim.x + threadIdx.x;
    if (e < EE) atomicAdd(&g_cnt[ei[EE + e]], 1);
}

__global__ void k_scan() {
    __shared__ int sh[1024];
    int tid = threadIdx.x;
    int off = 0;
    for (int base = 0; base < NN; base += 1024) {
        int i = base + tid;
        int v = (i < NN) ? g_cnt[i] : 0;
        sh[tid] = v;
        __syncthreads();
        for (int s = 1; s < 1024; s <<= 1) {
            int t = (tid >= s) ? sh[tid - s] : 0;
            __syncthreads();
            sh[tid] += t;
            __syncthreads();
        }
        if (i < NN) {
            int excl = off + sh[tid] - v;
            g_rowstart[i] = excl;
            g_cursor[i] = excl;
        }
        int tot = sh[1023];
        __syncthreads();
        off += tot;
    }
    if (tid == 0) g_rowstart[NN] = off;
}

__global__ void k_dinv() {
    int i = blockIdx.x * blockDim.x + threadIdx.x;
    if (i < NN) g_dinv[i] = rsqrtf((float)(g_cnt[i] + 1));
}

__global__ void k_fill(const int* __restrict__ ei) {
    int e = blockIdx.x * blockDim.x + threadIdx.x;
    if (e < EE) {
        int s = ei[e];
        int d = ei[EE + e];
        int pos = atomicAdd(&g_cursor[d], 1);
        g_csrsrc[pos] = s;
    }
}

// ---------------- first-layer linear (K = 3) ----------------
__global__ void k_lin3(const float* __restrict__ x, const float* __restrict__ w,
                       float* __restrict__ T) {
    int n = blockIdx.x;
    float x0 = x[n * 3 + 0], x1 = x[n * 3 + 1], x2 = x[n * 3 + 2];
    for (int f = threadIdx.x; f < HH; f += 256) {
        T[(size_t)n * HH + f] = x0 * w[f] + x1 * w[HH + f] + x2 * w[2 * HH + f];
    }
}

// ---------------- weight transpose + split ----------------
__global__ void k_split_w(const float* __restrict__ w,
                          __nv_bfloat16* __restrict__ th,
                          __nv_bfloat16* __restrict__ tl) {
    int idx = blockIdx.x * 256 + threadIdx.x;
    int n = idx / HH, k = idx % HH;
    float v = w[(size_t)k * HH + n];
    __nv_bfloat16 h = __float2bfloat16(v);
    th[idx] = h;
    tl[idx] = __float2bfloat16(v - __bfloat162float(h));
}

// ---------------- mma.sync GEMM: C[M,768] = A[M,768] @ W[768,768] --------------
// A as hi/lo bf16 [M,768]; W transposed hi/lo bf16 [768(N),768(K)].
// acc += Ah*Bh + Ah*Bl + Al*Bh  (fp32 accumulators); 3-stage cp.async pipeline.
#define GBM 128
#define GBN 128
#define GBK 32
#define KIT (HH / GBK)          // 24
#define TROW 40                 // padded row (bf16 elems): 80 bytes
#define TSZ (GBM * TROW)        // 5120 bf16 elems per tile
#define NSTG 3
#define STGB (4 * TSZ * 2)      // 40960 bytes per stage
#define MMA_SMEM (NSTG * STGB)  // 122880 bytes

__device__ __forceinline__ void ldsm4(uint32_t* r, uint32_t addr) {
    asm volatile("ldmatrix.sync.aligned.m8n8.x4.shared.b16 {%0,%1,%2,%3}, [%4];"
                 : "=r"(r[0]), "=r"(r[1]), "=r"(r[2]), "=r"(r[3]) : "r"(addr));
}
__device__ __forceinline__ void mma16816(float* c, const uint32_t* a, uint32_t b0,
                                         uint32_t b1) {
    asm volatile(
        "mma.sync.aligned.m16n8k16.row.col.f32.bf16.bf16.f32 "
        "{%0,%1,%2,%3}, {%4,%5,%6,%7}, {%8,%9}, {%0,%1,%2,%3};"
        : "+f"(c[0]), "+f"(c[1]), "+f"(c[2]), "+f"(c[3])
        : "r"(a[0]), "r"(a[1]), "r"(a[2]), "r"(a[3]), "r"(b0), "r"(b1));
}
__device__ __forceinline__ void cpa16(uint32_t dst, const void* src, int sz) {
    asm volatile("cp.async.cg.shared.global [%0], [%1], 16, %2;"
                 :: "r"(dst), "l"(src), "r"(sz) : "memory");
}

__global__ __launch_bounds__(256) void k_mma_gemm(const __nv_bfloat16* __restrict__ Ah,
                                                  const __nv_bfloat16* __restrict__ Al,
                                                  const __nv_bfloat16* __restrict__ Bh,
                                                  const __nv_bfloat16* __restrict__ Bl,
                                                  float* __restrict__ C) {
    extern __shared__ char smem[];
    uint32_t sb;
    asm("{ .reg .u64 t; cvta.to.shared.u64 t, %1; cvt.u32.u64 %0, t; }"
        : "=r"(sb) : "l"(smem));
    int tid = threadIdx.x;
    int lane = tid & 31, wid = tid >> 5;
    int wm = wid & 1, wn = wid >> 1;
    // column-block fast-varying: CTAs sharing the same A tile run concurrently
    int row0 = blockIdx.y * GBM;
    int col0 = blockIdx.x * GBN;

    float acc[4][4][4];
#pragma unroll
    for (int i = 0; i < 4; i++)
#pragma unroll
        for (int j = 0; j < 4; j++)
#pragma unroll
            for (int q = 0; q < 4; q++) acc[i][j][q] = 0.f;

    int vr = tid >> 2;          // row handled by this thread's vectors
    int vc = (tid & 3) * 8;     // bf16 col within 32-wide chunk
    int grA = row0 + vr;
    int okA = (grA < NN) ? 16 : 0;
    const char* pAh0 = (const char*)(Ah + (size_t)(okA ? grA : 0) * HH + vc);
    const char* pAl0 = (const char*)(Al + (size_t)(okA ? grA : 0) * HH + vc);
    const char* pBh0 = (const char*)(Bh + (size_t)(col0 + vr) * HH + vc);
    const char* pBl0 = (const char*)(Bl + (size_t)(col0 + vr) * HH + vc);
    int grA2 = row0 + vr + 64;
    int okA2 = (grA2 < NN) ? 16 : 0;
    const char* pAh1 = (const char*)(Ah + (size_t)(okA2 ? grA2 : 0) * HH + vc);
    const char* pAl1 = (const char*)(Al + (size_t)(okA2 ? grA2 : 0) * HH + vc);
    const char* pBh1 = (const char*)(Bh + (size_t)(col0 + vr + 64) * HH + vc);
    const char* pBl1 = (const char*)(Bl + (size_t)(col0 + vr + 64) * HH + vc);
    uint32_t d0 = sb + (vr * TROW + vc) * 2;
    uint32_t d1 = sb + ((vr + 64) * TROW + vc) * 2;

#define LOAD_TILES(stg, kbyte)                                                  \
    do {                                                                        \
        uint32_t bo = (stg) * STGB;                                             \
        cpa16(bo + d0 + 0 * TSZ * 2, pAh0 + (kbyte), okA);                      \
        cpa16(bo + d1 + 0 * TSZ * 2, pAh1 + (kbyte), okA2);                     \
        cpa16(bo + d0 + 1 * TSZ * 2, pAl0 + (kbyte), okA);                      \
        cpa16(bo + d1 + 1 * TSZ * 2, pAl1 + (kbyte), okA2);                     \
        cpa16(bo + d0 + 2 * TSZ * 2, pBh0 + (kbyte), 16);                       \
        cpa16(bo + d1 + 2 * TSZ * 2, pBh1 + (kbyte), 16);                       \
        cpa16(bo + d0 + 3 * TSZ * 2, pBl0 + (kbyte), 16);                       \
        cpa16(bo + d1 + 3 * TSZ * 2, pBl1 + (kbyte), 16);                       \
        asm volatile("cp.async.commit_group;" ::: "memory");                    \
    } while (0)

    LOAD_TILES(0, 0);
    LOAD_TILES(1, GBK * 2);

    int ar = lane & 15;
    int kc = (lane >> 4) * 8;

    for (int kt = 0; kt < KIT; kt++) {
        asm volatile("cp.async.wait_group 1;" ::: "memory");
        __syncthreads();
        if (kt + 2 < KIT) {
            int stg = (kt + 2) % NSTG;
            LOAD_TILES(stg, (kt + 2) * GBK * 2);
        }

        uint32_t tb = sb + (kt % NSTG) * STGB;
#pragma unroll
        for (int ks = 0; ks < 2; ks++) {
            int kb = ks * 16 + kc;
            uint32_t bh[2][4], bl_[2][4], af[4][4];
#pragma unroll
            for (int nb = 0; nb < 2; nb++) {
                uint32_t addr =
                    tb + 2 * TSZ * 2 + ((wn * 32 + nb * 16 + ar) * TROW + kb) * 2;
                ldsm4(bh[nb], addr);
                ldsm4(bl_[nb], addr + TSZ * 2);
            }
#pragma unroll
            for (int mf = 0; mf < 4; mf++)
                ldsm4(af[mf], tb + ((wm * 64 + mf * 16 + ar) * TROW + kb) * 2);
#pragma unroll
            for (int mf = 0; mf < 4; mf++)
#pragma unroll
                for (int nb = 0; nb < 2; nb++)
#pragma unroll
                    for (int h = 0; h < 2; h++) {
                        float* cc = acc[mf][nb * 2 + h];
                        mma16816(cc, af[mf], bh[nb][h], bh[nb][h + 2]);
                        mma16816(cc, af[mf], bl_[nb][h], bl_[nb][h + 2]);
                    }
#pragma unroll
            for (int mf = 0; mf < 4; mf++)
                ldsm4(af[mf],
                      tb + TSZ * 2 + ((wm * 64 + mf * 16 + ar) * TROW + kb) * 2);
#pragma unroll
            for (int mf = 0; mf < 4; mf++)
#pragma unroll
                for (int nb = 0; nb < 2; nb++)
#pragma unroll
                    for (int h = 0; h < 2; h++)
                        mma16816(acc[mf][nb * 2 + h], af[mf], bh[nb][h],
                                 bh[nb][h + 2]);
        }
    }
    __syncthreads();

    // epilogue: stage each 128x32 column block in smem, store coalesced
    float* stage = (float*)smem;
    for (int cb = 0; cb < 4; cb++) {
        if (wn == cb) {
            int r0r = wm * 64 + (lane >> 2);
            int c0c = (lane & 3) * 2;
#pragma unroll
            for (int mf = 0; mf < 4; mf++)
#pragma unroll
                for (int nf = 0; nf < 4; nf++) {
                    float* cc = acc[mf][nf];
                    int rr = r0r + mf * 16;
                    int ccol = nf * 8 + c0c;
                    stage[rr * 33 + ccol] = cc[0];
                    stage[rr * 33 + ccol + 1] = cc[1];
                    stage[(rr + 8) * 33 + ccol] = cc[2];
                    stage[(rr + 8) * 33 + ccol + 1] = cc[3];
                }
        }
        __syncthreads();
#pragma unroll
        for (int j = 0; j < 16; j++) {
            int e = tid + 256 * j;
            int rr = e >> 5, ccol = e & 31;
            int gr = row0 + rr;
            if (gr < NN)
                C[(size_t)gr * HH + col0 + cb * 32 + ccol] = stage[rr * 33 + ccol];
        }
        __syncthreads();
    }
}

// ---------------- GCN aggregation (+bias+relu) -> bf16 hi/lo split -------------
__global__ __launch_bounds__(256) void k_gcn_agg_bf(const float* __restrict__ T,
                                                    __nv_bfloat16* __restrict__ ah,
                                                    __nv_bfloat16* __restrict__ al,
                                                    const float* __restrict__ bias) {
    int n = blockIdx.x;
    float din = g_dinv[n];
    int s0 = g_rowstart[n], s1 = g_rowstart[n + 1];
    int f = threadIdx.x;
    float selfw = din * din;
    const float* rn = T + (size_t)n * HH;
    float a0 = rn[f] * selfw;
    float a1 = rn[f + 256] * selfw;
    float a2 = rn[f + 512] * selfw;
    for (int j = s0; j < s1; j++) {
        int s = g_csrsrc[j];
        float w = g_dinv[s] * din;
        const float* row = T + (size_t)s * HH;
        a0 += row[f] * w;
        a1 += row[f + 256] * w;
        a2 += row[f + 512] * w;
    }
    a0 = fmaxf(a0 + bias[f], 0.f);
    a1 = fmaxf(a1 + bias[f + 256], 0.f);
    a2 = fmaxf(a2 + bias[f + 512], 0.f);
    size_t base = (size_t)n * HH;
    float vv[3] = {a0, a1, a2};
#pragma unroll
    for (int c = 0; c < 3; c++) {
        __nv_bfloat16 h = __float2bfloat16(vv[c]);
        ah[base + f + c * 256] = h;
        al[base + f + c * 256] = __float2bfloat16(vv[c] - __bfloat162float(h));
    }
}

// ---------------- GAT alpha (per node, per head dot products) ----------------
__global__ void k_alpha(const float* __restrict__ Hg, const float* __restrict__ a_src,
                        const float* __restrict__ a_dst) {
    int gwarp = (blockIdx.x * blockDim.x + threadIdx.x) >> 5;
    int lane = threadIdx.x & 31;
    if (gwarp >= NN * NHD) return;
    int n = gwarp / NHD, h = gwarp % NHD;
    const float* row = Hg + (size_t)n * HH + h * HDD;
    float v0 = row[lane], v1 = row[lane + 32];
    float s = v0 * a_src[h * HDD + lane] + v1 * a_src[h * HDD + lane + 32];
    float d = v0 * a_dst[h * HDD + lane] + v1 * a_dst[h * HDD + lane + 32];
#pragma unroll
    for (int o = 16; o; o >>= 1) {
        s += __shfl_xor_sync(0xFFFFFFFFu, s, o);
        d += __shfl_xor_sync(0xFFFFFFFFu, d, o);
    }
    if (lane == 0) { g_as[gwarp] = s; g_ad[gwarp] = d; }
}

// ---------------- GAT aggregation (per-(edge,head) softmax weights in smem) ----
// mode 1: relu + write bf16 hi/lo (feeds next GEMM). mode 0: fp32 out, no relu.
#define CH 20
__global__ __launch_bounds__(256) void k_gat_agg(const float* __restrict__ Hg,
                                                 float* __restrict__ outf,
                                                 __nv_bfloat16* __restrict__ ah,
                                                 __nv_bfloat16* __restrict__ al,
                                                 const float* __restrict__ bias,
                                                 int mode) {
    __shared__ float sm[NHD], ssi[NHD], sself[NHD];
    __shared__ float swgt[CH][NHD];
    int n = blockIdx.x;
    int s0 = g_rowstart[n], s1 = g_rowstart[n + 1];
    int tid = threadIdx.x;

    if (tid < NHD) {
        float adn = g_ad[n * NHD + tid];
        float e_self = lrelu(g_as[n * NHD + tid] + adn);
        float m = e_self;
        for (int j = s0; j < s1; j++) {
            int s = g_csrsrc[j];
            float v = lrelu(g_as[s * NHD + tid] + adn);
            m = fmaxf(m, v);
        }
        float sum = __expf(e_self - m);
        for (int j = s0; j < s1; j++) {
            int s = g_csrsrc[j];
            sum += __expf(lrelu(g_as[s * NHD + tid] + adn) - m);
        }
        float inv = 1.0f / sum;
        sm[tid] = m;
        ssi[tid] = inv;
        sself[tid] = __expf(e_self - m) * inv;
    }
    __syncthreads();

    int h0 = tid >> 6;
    int h1 = (tid + 256) >> 6;
    int h2 = (tid + 512) >> 6;
    const float* rn = Hg + (size_t)n * HH;
    float acc0 = rn[tid] * sself[h0];
    float acc1 = rn[tid + 256] * sself[h1];
    float acc2v = rn[tid + 512] * sself[h2];

    for (int j0 = s0; j0 < s1; j0 += CH) {
        int cnt = min(CH, s1 - j0);
        if (tid < cnt * NHD) {
            int jj = tid / NHD, h = tid % NHD;
            int s = g_csrsrc[j0 + jj];
            swgt[jj][h] =
                __expf(lrelu(g_as[s * NHD + h] + g_ad[n * NHD + h]) - sm[h]) * ssi[h];
        }
        __syncthreads();
        for (int jj = 0; jj < cnt; jj++) {
            int s = g_csrsrc[j0 + jj];
            const float* row = Hg + (size_t)s * HH;
            acc0 += row[tid] * swgt[jj][h0];
            acc1 += row[tid + 256] * swgt[jj][h1];
            acc2v += row[tid + 512] * swgt[jj][h2];
        }
        __syncthreads();
    }

    float v0 = acc0 + bias[tid];
    float v1 = acc1 + bias[tid + 256];
    float v2 = acc2v + bias[tid + 512];
    size_t base = (size_t)n * HH;
    if (mode) {
        float vv[3] = {fmaxf(v0, 0.f), fmaxf(v1, 0.f), fmaxf(v2, 0.f)};
#pragma unroll
        for (int c = 0; c < 3; c++) {
            __nv_bfloat16 h = __float2bfloat16(vv[c]);
            ah[base + tid + c * 256] = h;
            al[base + tid + c * 256] = __float2bfloat16(vv[c] - __bfloat162float(h));
        }
    } else {
        outf[base + tid] = v0;
        outf[base + tid + 256] = v1;
        outf[base + tid + 512] = v2;
    }
}

// ---------------- global mean pool (sorted batch, binary search ranges) --------
__device__ __forceinline__ int lower_bound_batch(const int* b, int key) {
    int lo = 0, hi = NN;
    while (lo < hi) {
        int mid = (lo + hi) >> 1;
        if (b[mid] < key) lo = mid + 1; else hi = mid;
    }
    return lo;
}

__global__ void k_pool(const float* __restrict__ X, const int* __restrict__ batch) {
    int g = blockIdx.x / 12;
    int chunk = blockIdx.x % 12;
    int lo = lower_bound_batch(batch, g);
    int hi = lower_bound_batch(batch, g + 1);
    int f = chunk * 64 + threadIdx.x;
    float s = 0.f;
    for (int i = lo; i < hi; i++) s += X[(size_t)i * HH + f];
    float c = (float)((hi - lo) > 0 ? (hi - lo) : 1);
    g_pool[g * HH + f] = s / c;
}

// ---------------- classifier MLP ----------------
__global__ void k_mlp1(const float* __restrict__ wc1, const float* __restrict__ bc1) {
    __shared__ float sg[HH];
    int g = blockIdx.x;
    for (int i = threadIdx.x; i < HH; i += H2) sg[i] = g_pool[g * HH + i];
    __syncthreads();
    float acc = bc1[threadIdx.x];
    for (int k = 0; k < HH; k++) acc += sg[k] * wc1[k * H2 + threadIdx.x];
    g_zmlp[g * H2 + threadIdx.x] = fmaxf(acc, 0.f);
}

__global__ void k_mlp2(const float* __restrict__ wc2, const float* __restrict__ bc2,
                       float* __restrict__ out) {
    __shared__ float sz[H2];
    int g = blockIdx.x;
    for (int i = threadIdx.x; i < H2; i += 64) sz[i] = g_zmlp[g * H2 + i];
    __syncthreads();
    if (threadIdx.x < NCL) {
        float acc = bc2[threadIdx.x];
        for (int k = 0; k < H2; k++) acc += sz[k] * wc2[k * NCL + threadIdx.x];
        out[g * NCL + threadIdx.x] = acc;
    }
}

// ---------------- launch ----------------
extern "C" void kernel_launch(void* const* d_in, const int* in_sizes, int n_in,
                              void* d_out, int out_size) {
    const float* x    = (const float*)d_in[0];
    const int*   ei   = (const int*)d_in[1];
    const int*   batc = (const int*)d_in[2];
    const float* w1   = (const float*)d_in[3];
    const float* b1   = (const float*)d_in[4];
    const float* w2   = (const float*)d_in[5];
    const float* b2   = (const float*)d_in[6];
    const float* w3   = (const float*)d_in[7];
    const float* b3   = (const float*)d_in[8];
    const float* wg1  = (const float*)d_in[9];
    const float* as1  = (const float*)d_in[10];
    const float* ad1  = (const float*)d_in[11];
    const float* bg1  = (const float*)d_in[12];
    const float* wg2  = (const float*)d_in[13];
    const float* as2  = (const float*)d_in[14];
    const float* ad2  = (const float*)d_in[15];
    const float* bg2  = (const float*)d_in[16];
    const float* wc1  = (const float*)d_in[17];
    const float* bc1  = (const float*)d_in[18];
    const float* wc2  = (const float*)d_in[19];
    const float* bc2  = (const float*)d_in[20];
    float* out = (float*)d_out;

    float *bufA, *bufB;
    __nv_bfloat16 *Ah, *Al, *Wh, *Wl;
    cudaGetSymbolAddress((void**)&bufA, g_bufA);
    cudaGetSymbolAddress((void**)&bufB, g_bufB);
    cudaGetSymbolAddress((void**)&Ah, g_Ah);
    cudaGetSymbolAddress((void**)&Al, g_Al);
    cudaGetSymbolAddress((void**)&Wh, g_Wh);
    cudaGetSymbolAddress((void**)&Wl, g_Wl);

    cudaFuncSetAttribute(k_mma_gemm, cudaFuncAttributeMaxDynamicSharedMemorySize,
                         MMA_SMEM);

    dim3 tc_grid(HH / GBN, (NN + GBM - 1) / GBM);   // x = col (fast), y = row
    int splitW_blocks = (HH * HH) / 256;

    // CSR build
    k_zero_cnt<<<(NN + 255) / 256, 256>>>();
    k_count<<<(EE + 255) / 256, 256>>>(ei);
    k_scan<<<1, 1024>>>();
    k_dinv<<<(NN + 255) / 256, 256>>>();
    k_fill<<<(EE + 255) / 256, 256>>>(ei);

    // GCN layer 1: x[N,3] -> bufB -> agg -> Ah/Al
    k_lin3<<<NN, 256>>>(x, w1, bufB);
    k_gcn_agg_bf<<<NN, 256>>>(bufB, Ah, Al, b1);

    // GCN layer 2
    k_split_w<<<splitW_blocks, 256>>>(w2, Wh, Wl);
    k_mma_gemm<<<tc_grid, 256, MMA_SMEM>>>(Ah, Al, Wh, Wl, bufB);
    k_gcn_agg_bf<<<NN, 256>>>(bufB, Ah, Al, b2);

    // GCN layer 3
    k_split_w<<<splitW_blocks, 256>>>(w3, Wh, Wl);
    k_mma_gemm<<<tc_grid, 256, MMA_SMEM>>>(Ah, Al, Wh, Wl, bufB);
    k_gcn_agg_bf<<<NN, 256>>>(bufB, Ah, Al, b3);

    // GAT layer 1: gemm -> bufB (Hg) ; alpha ; agg -> Ah/Al (relu)
    k_split_w<<<splitW_blocks, 256>>>(wg1, Wh, Wl);
    k_mma_gemm<<<tc_grid, 256, MMA_SMEM>>>(Ah, Al, Wh, Wl, bufB);
    k_alpha<<<(NN * NHD * 32 + 255) / 256, 256>>>(bufB, as1, ad1);
    k_gat_agg<<<NN, 256>>>(bufB, nullptr, Ah, Al, bg1, 1);

    // GAT layer 2: gemm -> bufB ; alpha ; agg -> bufA (fp32, no relu)
    k_split_w<<<splitW_blocks, 256>>>(wg2, Wh, Wl);
    k_mma_gemm<<<tc_grid, 256, MMA_SMEM>>>(Ah, Al, Wh, Wl, bufB);
    k_alpha<<<(NN * NHD * 32 + 255) / 256, 256>>>(bufB, as2, ad2);
    k_gat_agg<<<NN, 256>>>(bufB, bufA, nullptr, nullptr, bg2, 0);

    // pool + MLP
    k_pool<<<NGR * 12, 64>>>(bufA, batc);
    k_mlp1<<<NGR, H2>>>(wc1, bc1);
    k_mlp2<<<NGR, 64>>>(wc2, bc2, out);
}

// round 8
// speedup vs baseline: 1.6518x; 1.6518x over previous
#include <cuda_runtime.h>
#include <cuda_bf16.h>
#include <math.h>
#include <stdint.h>

#define NN 50000
#define EE 100000
#define HH 768
#define NHD 12
#define HDD 64
#define NGR 64
#define NCL 10
#define H2 384

// ---------------- scratch (static device globals; no allocation) ----------------
__device__ float g_bufA[(size_t)NN * HH];
__device__ float g_bufB[(size_t)NN * HH];
__device__ __nv_bfloat16 g_Ah[(size_t)NN * HH];
__device__ __nv_bfloat16 g_Al[(size_t)NN * HH];
__device__ __nv_bfloat16 g_Wh[(size_t)HH * HH];   // transposed: [N=768][K=768]
__device__ __nv_bfloat16 g_Wl[(size_t)HH * HH];
__device__ float g_dinv[NN];
__device__ int   g_cnt[NN];
__device__ int   g_rowstart[NN + 1];
__device__ int   g_cursor[NN];
__device__ int   g_csrsrc[EE];
__device__ float g_as[NN * NHD];
__device__ float g_ad[NN * NHD];
__device__ float g_pool[NGR * HH];
__device__ float g_zmlp[NGR * H2];

__device__ __forceinline__ float lrelu(float x) { return x > 0.f ? x : 0.2f * x; }

// ---------------- CSR build ----------------
__global__ void k_zero_cnt() {
    int i = blockIdx.x * blockDim.x + threadIdx.x;
    if (i < NN) g_cnt[i] = 0;
}

__global__ void k_count(const int* __restrict__ ei) {
    int e = blockIdx.x * blockDim.x + threadIdx.x;
    if (e < EE) atomicAdd(&g_cnt[ei[EE + e]], 1);
}

__global__ void k_scan() {
    __shared__ int sh[1024];
    int tid = threadIdx.x;
    int off = 0;
    for (int base = 0; base < NN; base += 1024) {
        int i = base + tid;
        int v = (i < NN) ? g_cnt[i] : 0;
        sh[tid] = v;
        __syncthreads();
        for (int s = 1; s < 1024; s <<= 1) {
            int t = (tid >= s) ? sh[tid - s] : 0;
            __syncthreads();
            sh[tid] += t;
            __syncthreads();
        }
        if (i < NN) {
            int excl = off + sh[tid] - v;
            g_rowstart[i] = excl;
            g_cursor[i] = excl;
        }
        int tot = sh[1023];
        __syncthreads();
        off += tot;
    }
    if (tid == 0) g_rowstart[NN] = off;
}

__global__ void k_dinv() {
    int i = blockIdx.x * blockDim.x + threadIdx.x;
    if (i < NN) g_dinv[i] = rsqrtf((float)(g_cnt[i] + 1));
}

__global__ void k_fill(const int* __restrict__ ei) {
    int e = blockIdx.x * blockDim.x + threadIdx.x;
    if (e < EE) {
        int s = ei[e];
        int d = ei[EE + e];
        int pos = atomicAdd(&g_cursor[d], 1);
        g_csrsrc[pos] = s;
    }
}

// ---------------- first-layer linear (K = 3) ----------------
__global__ void k_lin3(const float* __restrict__ x, const float* __restrict__ w,
                       float* __restrict__ T) {
    int n = blockIdx.x;
    float x0 = x[n * 3 + 0], x1 = x[n * 3 + 1], x2 = x[n * 3 + 2];
    for (int f = threadIdx.x; f < HH; f += 256) {
        T[(size_t)n * HH + f] = x0 * w[f] + x1 * w[HH + f] + x2 * w[2 * HH + f];
    }
}

// ---------------- weight transpose + split ----------------
__global__ void k_split_w(const float* __restrict__ w,
                          __nv_bfloat16* __restrict__ th,
                          __nv_bfloat16* __restrict__ tl) {
    int idx = blockIdx.x * 256 + threadIdx.x;
    int n = idx / HH, k = idx % HH;
    float v = w[(size_t)k * HH + n];
    __nv_bfloat16 h = __float2bfloat16(v);
    th[idx] = h;
    tl[idx] = __float2bfloat16(v - __bfloat162float(h));
}

// ---------------- mma.sync GEMM: C[M,768] = A[M,768] @ W[768,768] --------------
// A as hi/lo bf16 [M,768]; W transposed hi/lo bf16 [768(N),768(K)].
// acc += Ah*Bh + Ah*Bl + Al*Bh  (fp32 accumulators)  [R6 configuration]
#define GBM 128
#define GBN 128
#define GBK 32
#define KIT (HH / GBK)          // 24
#define TROW 40                 // padded row (bf16 elems): 80 bytes
#define TSZ (GBM * TROW)        // 5120 bf16 elems per tile
#define MMA_SMEM (8 * TSZ * 2)  // 81920 bytes: [2 bufs][4 tensors]

__device__ __forceinline__ void ldsm4(uint32_t* r, uint32_t addr) {
    asm volatile("ldmatrix.sync.aligned.m8n8.x4.shared.b16 {%0,%1,%2,%3}, [%4];"
                 : "=r"(r[0]), "=r"(r[1]), "=r"(r[2]), "=r"(r[3]) : "r"(addr));
}
__device__ __forceinline__ void mma16816(float* c, const uint32_t* a, uint32_t b0,
                                         uint32_t b1) {
    asm volatile(
        "mma.sync.aligned.m16n8k16.row.col.f32.bf16.bf16.f32 "
        "{%0,%1,%2,%3}, {%4,%5,%6,%7}, {%8,%9}, {%0,%1,%2,%3};"
        : "+f"(c[0]), "+f"(c[1]), "+f"(c[2]), "+f"(c[3])
        : "r"(a[0]), "r"(a[1]), "r"(a[2]), "r"(a[3]), "r"(b0), "r"(b1));
}
__device__ __forceinline__ void cpa16(uint32_t dst, const void* src, int sz) {
    asm volatile("cp.async.ca.shared.global [%0], [%1], 16, %2;"
                 :: "r"(dst), "l"(src), "r"(sz) : "memory");
}

__global__ __launch_bounds__(256) void k_mma_gemm(const __nv_bfloat16* __restrict__ Ah,
                                                  const __nv_bfloat16* __restrict__ Al,
                                                  const __nv_bfloat16* __restrict__ Bh,
                                                  const __nv_bfloat16* __restrict__ Bl,
                                                  float* __restrict__ C) {
    extern __shared__ char smem[];
    uint32_t sb;
    asm("{ .reg .u64 t; cvta.to.shared.u64 t, %1; cvt.u32.u64 %0, t; }"
        : "=r"(sb) : "l"(smem));
    int tid = threadIdx.x;
    int lane = tid & 31, wid = tid >> 5;
    int wm = wid & 1, wn = wid >> 1;
    int row0 = blockIdx.x * GBM;
    int col0 = blockIdx.y * GBN;

    float acc[4][4][4];
#pragma unroll
    for (int i = 0; i < 4; i++)
#pragma unroll
        for (int j = 0; j < 4; j++)
#pragma unroll
            for (int q = 0; q < 4; q++) acc[i][j][q] = 0.f;

    int vr = tid >> 2;          // row handled by this thread's vectors
    int vc = (tid & 3) * 8;     // bf16 col within 32-wide chunk
    int grA = row0 + vr;
    int okA = (grA < NN) ? 16 : 0;
    const char* pAh0 = (const char*)(Ah + (size_t)(okA ? grA : 0) * HH + vc);
    const char* pAl0 = (const char*)(Al + (size_t)(okA ? grA : 0) * HH + vc);
    const char* pBh0 = (const char*)(Bh + (size_t)(col0 + vr) * HH + vc);
    const char* pBl0 = (const char*)(Bl + (size_t)(col0 + vr) * HH + vc);
    int grA2 = row0 + vr + 64;
    int okA2 = (grA2 < NN) ? 16 : 0;
    const char* pAh1 = (const char*)(Ah + (size_t)(okA2 ? grA2 : 0) * HH + vc);
    const char* pAl1 = (const char*)(Al + (size_t)(okA2 ? grA2 : 0) * HH + vc);
    const char* pBh1 = (const char*)(Bh + (size_t)(col0 + vr + 64) * HH + vc);
    const char* pBl1 = (const char*)(Bl + (size_t)(col0 + vr + 64) * HH + vc);
    uint32_t d0 = sb + (vr * TROW + vc) * 2;
    uint32_t d1 = sb + ((vr + 64) * TROW + vc) * 2;

#define LOAD_TILES(buf, kbyte)                                                  \
    do {                                                                        \
        uint32_t bo = (buf) * (4 * TSZ * 2);                                    \
        cpa16(bo + d0 + 0 * TSZ * 2, pAh0 + (kbyte), okA);                      \
        cpa16(bo + d1 + 0 * TSZ * 2, pAh1 + (kbyte), okA2);                     \
        cpa16(bo + d0 + 1 * TSZ * 2, pAl0 + (kbyte), okA);                      \
        cpa16(bo + d1 + 1 * TSZ * 2, pAl1 + (kbyte), okA2);                     \
        cpa16(bo + d0 + 2 * TSZ * 2, pBh0 + (kbyte), 16);                       \
        cpa16(bo + d1 + 2 * TSZ * 2, pBh1 + (kbyte), 16);                       \
        cpa16(bo + d0 + 3 * TSZ * 2, pBl0 + (kbyte), 16);                       \
        cpa16(bo + d1 + 3 * TSZ * 2, pBl1 + (kbyte), 16);                       \
        asm volatile("cp.async.commit_group;" ::: "memory");                    \
    } while (0)

    LOAD_TILES(0, 0);

    int ar = lane & 15;
    int kc = (lane >> 4) * 8;

    for (int kt = 0; kt < KIT; kt++) {
        if (kt + 1 < KIT) LOAD_TILES((kt + 1) & 1, (kt + 1) * GBK * 2);
        if (kt + 1 < KIT)
            asm volatile("cp.async.wait_group 1;" ::: "memory");
        else
            asm volatile("cp.async.wait_group 0;" ::: "memory");
        __syncthreads();

        uint32_t tb = sb + (kt & 1) * (4 * TSZ * 2);
#pragma unroll
        for (int ks = 0; ks < 2; ks++) {
            int kb = ks * 16 + kc;
            uint32_t bh[2][4], bl_[2][4], af[4][4];
#pragma unroll
            for (int nb = 0; nb < 2; nb++) {
                uint32_t addr =
                    tb + 2 * TSZ * 2 + ((wn * 32 + nb * 16 + ar) * TROW + kb) * 2;
                ldsm4(bh[nb], addr);
                ldsm4(bl_[nb], addr + TSZ * 2);
            }
#pragma unroll
            for (int mf = 0; mf < 4; mf++)
                ldsm4(af[mf], tb + ((wm * 64 + mf * 16 + ar) * TROW + kb) * 2);
#pragma unroll
            for (int mf = 0; mf < 4; mf++)
#pragma unroll
                for (int nb = 0; nb < 2; nb++)
#pragma unroll
                    for (int h = 0; h < 2; h++) {
                        float* cc = acc[mf][nb * 2 + h];
                        mma16816(cc, af[mf], bh[nb][h], bh[nb][h + 2]);
                        mma16816(cc, af[mf], bl_[nb][h], bl_[nb][h + 2]);
                    }
#pragma unroll
            for (int mf = 0; mf < 4; mf++)
                ldsm4(af[mf],
                      tb + TSZ * 2 + ((wm * 64 + mf * 16 + ar) * TROW + kb) * 2);
#pragma unroll
            for (int mf = 0; mf < 4; mf++)
#pragma unroll
                for (int nb = 0; nb < 2; nb++)
#pragma unroll
                    for (int h = 0; h < 2; h++)
                        mma16816(acc[mf][nb * 2 + h], af[mf], bh[nb][h],
                                 bh[nb][h + 2]);
        }
        __syncthreads();
    }

    // epilogue: stage each 128x32 column block in smem, store coalesced
    float* stage = (float*)smem;
    for (int cb = 0; cb < 4; cb++) {
        if (wn == cb) {
            int r0r = wm * 64 + (lane >> 2);
            int c0c = (lane & 3) * 2;
#pragma unroll
            for (int mf = 0; mf < 4; mf++)
#pragma unroll
                for (int nf = 0; nf < 4; nf++) {
                    float* cc = acc[mf][nf];
                    int rr = r0r + mf * 16;
                    int ccol = nf * 8 + c0c;
                    stage[rr * 33 + ccol] = cc[0];
                    stage[rr * 33 + ccol + 1] = cc[1];
                    stage[(rr + 8) * 33 + ccol] = cc[2];
                    stage[(rr + 8) * 33 + ccol + 1] = cc[3];
                }
        }
        __syncthreads();
#pragma unroll
        for (int j = 0; j < 16; j++) {
            int e = tid + 256 * j;
            int rr = e >> 5, ccol = e & 31;
            int gr = row0 + rr;
            if (gr < NN)
                C[(size_t)gr * HH + col0 + cb * 32 + ccol] = stage[rr * 33 + ccol];
        }
        __syncthreads();
    }
}

// ---------------- GCN aggregation (+bias+relu) -> bf16 hi/lo split -------------
__global__ __launch_bounds__(256) void k_gcn_agg_bf(const float* __restrict__ T,
                                                    __nv_bfloat16* __restrict__ ah,
                                                    __nv_bfloat16* __restrict__ al,
                                                    const float* __restrict__ bias) {
    int n = blockIdx.x;
    float din = g_dinv[n];
    int s0 = g_rowstart[n], s1 = g_rowstart[n + 1];
    int f = threadIdx.x;
    float selfw = din * din;
    const float* rn = T + (size_t)n * HH;
    float a0 = rn[f] * selfw;
    float a1 = rn[f + 256] * selfw;
    float a2 = rn[f + 512] * selfw;
    for (int j = s0; j < s1; j++) {
        int s = g_csrsrc[j];
        float w = g_dinv[s] * din;
        const float* row = T + (size_t)s * HH;
        a0 += row[f] * w;
        a1 += row[f + 256] * w;
        a2 += row[f + 512] * w;
    }
    a0 = fmaxf(a0 + bias[f], 0.f);
    a1 = fmaxf(a1 + bias[f + 256], 0.f);
    a2 = fmaxf(a2 + bias[f + 512], 0.f);
    size_t base = (size_t)n * HH;
    float vv[3] = {a0, a1, a2};
#pragma unroll
    for (int c = 0; c < 3; c++) {
        __nv_bfloat16 h = __float2bfloat16(vv[c]);
        ah[base + f + c * 256] = h;
        al[base + f + c * 256] = __float2bfloat16(vv[c] - __bfloat162float(h));
    }
}

// ---------------- GAT alpha (per node, per head dot products) ----------------
__global__ void k_alpha(const float* __restrict__ Hg, const float* __restrict__ a_src,
                        const float* __restrict__ a_dst) {
    int gwarp = (blockIdx.x * blockDim.x + threadIdx.x) >> 5;
    int lane = threadIdx.x & 31;
    if (gwarp >= NN * NHD) return;
    int n = gwarp / NHD, h = gwarp % NHD;
    const float* row = Hg + (size_t)n * HH + h * HDD;
    float v0 = row[lane], v1 = row[lane + 32];
    float s = v0 * a_src[h * HDD + lane] + v1 * a_src[h * HDD + lane + 32];
    float d = v0 * a_dst[h * HDD + lane] + v1 * a_dst[h * HDD + lane + 32];
#pragma unroll
    for (int o = 16; o; o >>= 1) {
        s += __shfl_xor_sync(0xFFFFFFFFu, s, o);
        d += __shfl_xor_sync(0xFFFFFFFFu, d, o);
    }
    if (lane == 0) { g_as[gwarp] = s; g_ad[gwarp] = d; }
}

// ---------------- GAT aggregation (per-(edge,head) softmax weights in smem) ----
// mode 1: relu + write bf16 hi/lo (feeds next GEMM). mode 0: fp32 out, no relu.
#define CH 20
__global__ __launch_bounds__(256) void k_gat_agg(const float* __restrict__ Hg,
                                                 float* __restrict__ outf,
                                                 __nv_bfloat16* __restrict__ ah,
                                                 __nv_bfloat16* __restrict__ al,
                                                 const float* __restrict__ bias,
                                                 int mode) {
    __shared__ float sm[NHD], ssi[NHD], sself[NHD];
    __shared__ float swgt[CH][NHD];
    int n = blockIdx.x;
    int s0 = g_rowstart[n], s1 = g_rowstart[n + 1];
    int tid = threadIdx.x;

    if (tid < NHD) {
        float adn = g_ad[n * NHD + tid];
        float e_self = lrelu(g_as[n * NHD + tid] + adn);
        float m = e_self;
        for (int j = s0; j < s1; j++) {
            int s = g_csrsrc[j];
            float v = lrelu(g_as[s * NHD + tid] + adn);
            m = fmaxf(m, v);
        }
        float sum = __expf(e_self - m);
        for (int j = s0; j < s1; j++) {
            int s = g_csrsrc[j];
            sum += __expf(lrelu(g_as[s * NHD + tid] + adn) - m);
        }
        float inv = 1.0f / sum;
        sm[tid] = m;
        ssi[tid] = inv;
        sself[tid] = __expf(e_self - m) * inv;
    }
    __syncthreads();

    int h0 = tid >> 6;
    int h1 = (tid + 256) >> 6;
    int h2 = (tid + 512) >> 6;
    const float* rn = Hg + (size_t)n * HH;
    float acc0 = rn[tid] * sself[h0];
    float acc1 = rn[tid + 256] * sself[h1];
    float acc2v = rn[tid + 512] * sself[h2];

    for (int j0 = s0; j0 < s1; j0 += CH) {
        int cnt = min(CH, s1 - j0);
        if (tid < cnt * NHD) {
            int jj = tid / NHD, h = tid % NHD;
            int s = g_csrsrc[j0 + jj];
            swgt[jj][h] =
                __expf(lrelu(g_as[s * NHD + h] + g_ad[n * NHD + h]) - sm[h]) * ssi[h];
        }
        __syncthreads();
        for (int jj = 0; jj < cnt; jj++) {
            int s = g_csrsrc[j0 + jj];
            const float* row = Hg + (size_t)s * HH;
            acc0 += row[tid] * swgt[jj][h0];
            acc1 += row[tid + 256] * swgt[jj][h1];
            acc2v += row[tid + 512] * swgt[jj][h2];
        }
        __syncthreads();
    }

    float v0 = acc0 + bias[tid];
    float v1 = acc1 + bias[tid + 256];
    float v2 = acc2v + bias[tid + 512];
    size_t base = (size_t)n * HH;
    if (mode) {
        float vv[3] = {fmaxf(v0, 0.f), fmaxf(v1, 0.f), fmaxf(v2, 0.f)};
#pragma unroll
        for (int c = 0; c < 3; c++) {
            __nv_bfloat16 h = __float2bfloat16(vv[c]);
            ah[base + tid + c * 256] = h;
            al[base + tid + c * 256] = __float2bfloat16(vv[c] - __bfloat162float(h));
        }
    } else {
        outf[base + tid] = v0;
        outf[base + tid + 256] = v1;
        outf[base + tid + 512] = v2;
    }
}

// ---------------- global mean pool (sorted batch, binary search ranges) --------
__device__ __forceinline__ int lower_bound_batch(const int* b, int key) {
    int lo = 0, hi = NN;
    while (lo < hi) {
        int mid = (lo + hi) >> 1;
        if (b[mid] < key) lo = mid + 1; else hi = mid;
    }
    return lo;
}

__global__ void k_pool(const float* __restrict__ X, const int* __restrict__ batch) {
    int g = blockIdx.x / 12;
    int chunk = blockIdx.x % 12;
    int lo = lower_bound_batch(batch, g);
    int hi = lower_bound_batch(batch, g + 1);
    int f = chunk * 64 + threadIdx.x;
    float s = 0.f;
    for (int i = lo; i < hi; i++) s += X[(size_t)i * HH + f];
    float c = (float)((hi - lo) > 0 ? (hi - lo) : 1);
    g_pool[g * HH + f] = s / c;
}

// ---------------- classifier MLP ----------------
__global__ void k_mlp1(const float* __restrict__ wc1, const float* __restrict__ bc1) {
    __shared__ float sg[HH];
    int g = blockIdx.x;
    for (int i = threadIdx.x; i < HH; i += H2) sg[i] = g_pool[g * HH + i];
    __syncthreads();
    float acc = bc1[threadIdx.x];
    for (int k = 0; k < HH; k++) acc += sg[k] * wc1[k * H2 + threadIdx.x];
    g_zmlp[g * H2 + threadIdx.x] = fmaxf(acc, 0.f);
}

__global__ void k_mlp2(const float* __restrict__ wc2, const float* __restrict__ bc2,
                       float* __restrict__ out) {
    __shared__ float sz[H2];
    int g = blockIdx.x;
    for (int i = threadIdx.x; i < H2; i += 64) sz[i] = g_zmlp[g * H2 + i];
    __syncthreads();
    if (threadIdx.x < NCL) {
        float acc = bc2[threadIdx.x];
        for (int k = 0; k < H2; k++) acc += sz[k] * wc2[k * NCL + threadIdx.x];
        out[g * NCL + threadIdx.x] = acc;
    }
}

// ---------------- launch ----------------
extern "C" void kernel_launch(void* const* d_in, const int* in_sizes, int n_in,
                              void* d_out, int out_size) {
    const float* x    = (const float*)d_in[0];
    const int*   ei   = (const int*)d_in[1];
    const int*   batc = (const int*)d_in[2];
    const float* w1   = (const float*)d_in[3];
    const float* b1   = (const float*)d_in[4];
    const float* w2   = (const float*)d_in[5];
    const float* b2   = (const float*)d_in[6];
    const float* w3   = (const float*)d_in[7];
    const float* b3   = (const float*)d_in[8];
    const float* wg1  = (const float*)d_in[9];
    const float* as1  = (const float*)d_in[10];
    const float* ad1  = (const float*)d_in[11];
    const float* bg1  = (const float*)d_in[12];
    const float* wg2  = (const float*)d_in[13];
    const float* as2  = (const float*)d_in[14];
    const float* ad2  = (const float*)d_in[15];
    const float* bg2  = (const float*)d_in[16];
    const float* wc1  = (const float*)d_in[17];
    const float* bc1  = (const float*)d_in[18];
    const float* wc2  = (const float*)d_in[19];
    const float* bc2  = (const float*)d_in[20];
    float* out = (float*)d_out;

    float *bufA, *bufB;
    __nv_bfloat16 *Ah, *Al, *Wh, *Wl;
    cudaGetSymbolAddress((void**)&bufA, g_bufA);
    cudaGetSymbolAddress((void**)&bufB, g_bufB);
    cudaGetSymbolAddress((void**)&Ah, g_Ah);
    cudaGetSymbolAddress((void**)&Al, g_Al);
    cudaGetSymbolAddress((void**)&Wh, g_Wh);
    cudaGetSymbolAddress((void**)&Wl, g_Wl);

    cudaFuncSetAttribute(k_mma_gemm, cudaFuncAttributeMaxDynamicSharedMemorySize,
                         MMA_SMEM);

    dim3 tc_grid((NN + GBM - 1) / GBM, HH / GBN);   // R6 grid order: x = row
    int splitW_blocks = (HH * HH) / 256;

    // CSR build
    k_zero_cnt<<<(NN + 255) / 256, 256>>>();
    k_count<<<(EE + 255) / 256, 256>>>(ei);
    k_scan<<<1, 1024>>>();
    k_dinv<<<(NN + 255) / 256, 256>>>();
    k_fill<<<(EE + 255) / 256, 256>>>(ei);

    // GCN layer 1: x[N,3] -> bufB -> agg -> Ah/Al
    k_lin3<<<NN, 256>>>(x, w1, bufB);
    k_gcn_agg_bf<<<NN, 256>>>(bufB, Ah, Al, b1);

    // GCN layer 2
    k_split_w<<<splitW_blocks, 256>>>(w2, Wh, Wl);
    k_mma_gemm<<<tc_grid, 256, MMA_SMEM>>>(Ah, Al, Wh, Wl, bufB);
    k_gcn_agg_bf<<<NN, 256>>>(bufB, Ah, Al, b2);

    // GCN layer 3
    k_split_w<<<splitW_blocks, 256>>>(w3, Wh, Wl);
    k_mma_gemm<<<tc_grid, 256, MMA_SMEM>>>(Ah, Al, Wh, Wl, bufB);
    k_gcn_agg_bf<<<NN, 256>>>(bufB, Ah, Al, b3);

    // GAT layer 1: gemm -> bufB (Hg) ; alpha ; agg -> Ah/Al (relu)
    k_split_w<<<splitW_blocks, 256>>>(wg1, Wh, Wl);
    k_mma_gemm<<<tc_grid, 256, MMA_SMEM>>>(Ah, Al, Wh, Wl, bufB);
    k_alpha<<<(NN * NHD * 32 + 255) / 256, 256>>>(bufB, as1, ad1);
    k_gat_agg<<<NN, 256>>>(bufB, nullptr, Ah, Al, bg1, 1);

    // GAT layer 2: gemm -> bufB ; alpha ; agg -> bufA (fp32, no relu)
    k_split_w<<<splitW_blocks, 256>>>(wg2, Wh, Wl);
    k_mma_gemm<<<tc_grid, 256, MMA_SMEM>>>(Ah, Al, Wh, Wl, bufB);
    k_alpha<<<(NN * NHD * 32 + 255) / 256, 256>>>(bufB, as2, ad2);
    k_gat_agg<<<NN, 256>>>(bufB, bufA, nullptr, nullptr, bg2, 0);

    // pool + MLP
    k_pool<<<NGR * 12, 64>>>(bufA, batc);
    k_mlp1<<<NGR, H2>>>(wc1, bc1);
    k_mlp2<<<NGR, 64>>>(wc2, bc2, out);
}

// round 9
// speedup vs baseline: 1.7687x; 1.0708x over previous
#include <cuda_runtime.h>
#include <cuda_bf16.h>
#include <math.h>
#include <stdint.h>

#define NN 50000
#define EE 100000
#define HH 768
#define NHD 12
#define HDD 64
#define NGR 64
#define NCL 10
#define H2 384

// ---------------- scratch (static device globals; no allocation) ----------------
__device__ float g_bufA[(size_t)NN * HH];
__device__ float g_bufB[(size_t)NN * HH];
__device__ __nv_bfloat16 g_Ah[(size_t)NN * HH];
__device__ __nv_bfloat16 g_Al[(size_t)NN * HH];
__device__ __nv_bfloat16 g_Wh[(size_t)HH * HH];   // transposed: [N=768][K=768]
__device__ __nv_bfloat16 g_Wl[(size_t)HH * HH];
__device__ float g_dinv[NN];
__device__ int   g_cnt[NN];
__device__ int   g_rowstart[NN + 1];
__device__ int   g_cursor[NN];
__device__ int   g_csrsrc[EE];
__device__ float g_as[NN * NHD];
__device__ float g_ad[NN * NHD];
__device__ float g_pool[NGR * HH];
__device__ float g_zmlp[NGR * H2];

__device__ __forceinline__ float lrelu(float x) { return x > 0.f ? x : 0.2f * x; }

// ---------------- CSR build ----------------
__global__ void k_zero_cnt() {
    int i = blockIdx.x * blockDim.x + threadIdx.x;
    if (i < NN) g_cnt[i] = 0;
}

__global__ void k_count(const int* __restrict__ ei) {
    int e = blockIdx.x * blockDim.x + threadIdx.x;
    if (e < EE) atomicAdd(&g_cnt[ei[EE + e]], 1);
}

__global__ void k_scan() {
    __shared__ int sh[1024];
    int tid = threadIdx.x;
    int off = 0;
    for (int base = 0; base < NN; base += 1024) {
        int i = base + tid;
        int v = (i < NN) ? g_cnt[i] : 0;
        sh[tid] = v;
        __syncthreads();
        for (int s = 1; s < 1024; s <<= 1) {
            int t = (tid >= s) ? sh[tid - s] : 0;
            __syncthreads();
            sh[tid] += t;
            __syncthreads();
        }
        if (i < NN) {
            int excl = off + sh[tid] - v;
            g_rowstart[i] = excl;
            g_cursor[i] = excl;
        }
        int tot = sh[1023];
        __syncthreads();
        off += tot;
    }
    if (tid == 0) g_rowstart[NN] = off;
}

__global__ void k_dinv() {
    int i = blockIdx.x * blockDim.x + threadIdx.x;
    if (i < NN) g_dinv[i] = rsqrtf((float)(g_cnt[i] + 1));
}

__global__ void k_fill(const int* __restrict__ ei) {
    int e = blockIdx.x * blockDim.x + threadIdx.x;
    if (e < EE) {
        int s = ei[e];
        int d = ei[EE + e];
        int pos = atomicAdd(&g_cursor[d], 1);
        g_csrsrc[pos] = s;
    }
}

// ---------------- fused GCN layer 1 (linearity: Agg(x@W) == Agg(x)@W) ---------
__global__ __launch_bounds__(256) void k_gcn_l1(const float* __restrict__ x,
                                                const float* __restrict__ w1,
                                                const float* __restrict__ b1,
                                                __nv_bfloat16* __restrict__ ah,
                                                __nv_bfloat16* __restrict__ al) {
    __shared__ float xb[3];
    int n = blockIdx.x;
    int tid = threadIdx.x;
    if (tid < 3) {
        float din = g_dinv[n];
        float acc = x[n * 3 + tid] * din * din;
        int s0 = g_rowstart[n], s1 = g_rowstart[n + 1];
        for (int j = s0; j < s1; j++) {
            int s = g_csrsrc[j];
            acc += x[s * 3 + tid] * g_dinv[s] * din;
        }
        xb[tid] = acc;
    }
    __syncthreads();
    float x0 = xb[0], x1 = xb[1], x2 = xb[2];
    size_t base = (size_t)n * HH;
#pragma unroll
    for (int c = 0; c < 3; c++) {
        int f = tid + c * 256;
        float v = x0 * w1[f] + x1 * w1[HH + f] + x2 * w1[2 * HH + f] + b1[f];
        v = fmaxf(v, 0.f);
        __nv_bfloat16 h = __float2bfloat16(v);
        ah[base + f] = h;
        al[base + f] = __float2bfloat16(v - __bfloat162float(h));
    }
}

// ---------------- weight transpose + split ----------------
__global__ void k_split_w(const float* __restrict__ w,
                          __nv_bfloat16* __restrict__ th,
                          __nv_bfloat16* __restrict__ tl) {
    int idx = blockIdx.x * 256 + threadIdx.x;
    int n = idx / HH, k = idx % HH;
    float v = w[(size_t)k * HH + n];
    __nv_bfloat16 h = __float2bfloat16(v);
    th[idx] = h;
    tl[idx] = __float2bfloat16(v - __bfloat162float(h));
}

// ---------------- mma.sync GEMM: C[M,768] = A[M,768] @ W[768,768] --------------
// A as hi/lo bf16 [M,768]; W transposed hi/lo bf16 [768(N),768(K)].
// acc += Ah*Bh + Ah*Bl + Al*Bh  (fp32 accumulators); 1 sync per k-tile.
#define GBM 128
#define GBN 128
#define GBK 32
#define KIT (HH / GBK)          // 24
#define TROW 40                 // padded row (bf16 elems): 80 bytes
#define TSZ (GBM * TROW)        // 5120 bf16 elems per tile
#define MMA_SMEM (8 * TSZ * 2)  // 81920 bytes: [2 bufs][4 tensors]

__device__ __forceinline__ void ldsm4(uint32_t* r, uint32_t addr) {
    asm volatile("ldmatrix.sync.aligned.m8n8.x4.shared.b16 {%0,%1,%2,%3}, [%4];"
                 : "=r"(r[0]), "=r"(r[1]), "=r"(r[2]), "=r"(r[3]) : "r"(addr));
}
__device__ __forceinline__ void mma16816(float* c, const uint32_t* a, uint32_t b0,
                                         uint32_t b1) {
    asm volatile(
        "mma.sync.aligned.m16n8k16.row.col.f32.bf16.bf16.f32 "
        "{%0,%1,%2,%3}, {%4,%5,%6,%7}, {%8,%9}, {%0,%1,%2,%3};"
        : "+f"(c[0]), "+f"(c[1]), "+f"(c[2]), "+f"(c[3])
        : "r"(a[0]), "r"(a[1]), "r"(a[2]), "r"(a[3]), "r"(b0), "r"(b1));
}
__device__ __forceinline__ void cpa16(uint32_t dst, const void* src, int sz) {
    asm volatile("cp.async.ca.shared.global [%0], [%1], 16, %2;"
                 :: "r"(dst), "l"(src), "r"(sz) : "memory");
}

__global__ __launch_bounds__(256) void k_mma_gemm(const __nv_bfloat16* __restrict__ Ah,
                                                  const __nv_bfloat16* __restrict__ Al,
                                                  const __nv_bfloat16* __restrict__ Bh,
                                                  const __nv_bfloat16* __restrict__ Bl,
                                                  float* __restrict__ C) {
    extern __shared__ char smem[];
    uint32_t sb;
    asm("{ .reg .u64 t; cvta.to.shared.u64 t, %1; cvt.u32.u64 %0, t; }"
        : "=r"(sb) : "l"(smem));
    int tid = threadIdx.x;
    int lane = tid & 31, wid = tid >> 5;
    int wm = wid & 1, wn = wid >> 1;
    int row0 = blockIdx.x * GBM;
    int col0 = blockIdx.y * GBN;

    float acc[4][4][4];
#pragma unroll
    for (int i = 0; i < 4; i++)
#pragma unroll
        for (int j = 0; j < 4; j++)
#pragma unroll
            for (int q = 0; q < 4; q++) acc[i][j][q] = 0.f;

    int vr = tid >> 2;          // row handled by this thread's vectors
    int vc = (tid & 3) * 8;     // bf16 col within 32-wide chunk
    int grA = row0 + vr;
    int okA = (grA < NN) ? 16 : 0;
    const char* pAh0 = (const char*)(Ah + (size_t)(okA ? grA : 0) * HH + vc);
    const char* pAl0 = (const char*)(Al + (size_t)(okA ? grA : 0) * HH + vc);
    const char* pBh0 = (const char*)(Bh + (size_t)(col0 + vr) * HH + vc);
    const char* pBl0 = (const char*)(Bl + (size_t)(col0 + vr) * HH + vc);
    int grA2 = row0 + vr + 64;
    int okA2 = (grA2 < NN) ? 16 : 0;
    const char* pAh1 = (const char*)(Ah + (size_t)(okA2 ? grA2 : 0) * HH + vc);
    const char* pAl1 = (const char*)(Al + (size_t)(okA2 ? grA2 : 0) * HH + vc);
    const char* pBh1 = (const char*)(Bh + (size_t)(col0 + vr + 64) * HH + vc);
    const char* pBl1 = (const char*)(Bl + (size_t)(col0 + vr + 64) * HH + vc);
    uint32_t d0 = sb + (vr * TROW + vc) * 2;
    uint32_t d1 = sb + ((vr + 64) * TROW + vc) * 2;

#define LOAD_TILES(buf, kbyte)                                                  \
    do {                                                                        \
        uint32_t bo = (buf) * (4 * TSZ * 2);                                    \
        cpa16(bo + d0 + 0 * TSZ * 2, pAh0 + (kbyte), okA);                      \
        cpa16(bo + d1 + 0 * TSZ * 2, pAh1 + (kbyte), okA2);                     \
        cpa16(bo + d0 + 1 * TSZ * 2, pAl0 + (kbyte), okA);                      \
        cpa16(bo + d1 + 1 * TSZ * 2, pAl1 + (kbyte), okA2);                     \
        cpa16(bo + d0 + 2 * TSZ * 2, pBh0 + (kbyte), 16);                       \
        cpa16(bo + d1 + 2 * TSZ * 2, pBh1 + (kbyte), 16);                       \
        cpa16(bo + d0 + 3 * TSZ * 2, pBl0 + (kbyte), 16);                       \
        cpa16(bo + d1 + 3 * TSZ * 2, pBl1 + (kbyte), 16);                       \
        asm volatile("cp.async.commit_group;" ::: "memory");                    \
    } while (0)

    LOAD_TILES(0, 0);

    int ar = lane & 15;
    int kc = (lane >> 4) * 8;

    for (int kt = 0; kt < KIT; kt++) {
        // drain LOAD(kt); sync doubles as the write-hazard guard for LOAD(kt+1)
        asm volatile("cp.async.wait_group 0;" ::: "memory");
        __syncthreads();
        if (kt + 1 < KIT) LOAD_TILES((kt + 1) & 1, (kt + 1) * GBK * 2);

        uint32_t tb = sb + (kt & 1) * (4 * TSZ * 2);
#pragma unroll
        for (int ks = 0; ks < 2; ks++) {
            int kb = ks * 16 + kc;
            uint32_t bh[2][4], bl_[2][4], af[4][4];
#pragma unroll
            for (int nb = 0; nb < 2; nb++) {
                uint32_t addr =
                    tb + 2 * TSZ * 2 + ((wn * 32 + nb * 16 + ar) * TROW + kb) * 2;
                ldsm4(bh[nb], addr);
                ldsm4(bl_[nb], addr + TSZ * 2);
            }
#pragma unroll
            for (int mf = 0; mf < 4; mf++)
                ldsm4(af[mf], tb + ((wm * 64 + mf * 16 + ar) * TROW + kb) * 2);
#pragma unroll
            for (int mf = 0; mf < 4; mf++)
#pragma unroll
                for (int nb = 0; nb < 2; nb++)
#pragma unroll
                    for (int h = 0; h < 2; h++) {
                        float* cc = acc[mf][nb * 2 + h];
                        mma16816(cc, af[mf], bh[nb][h], bh[nb][h + 2]);
                        mma16816(cc, af[mf], bl_[nb][h], bl_[nb][h + 2]);
                    }
#pragma unroll
            for (int mf = 0; mf < 4; mf++)
                ldsm4(af[mf],
                      tb + TSZ * 2 + ((wm * 64 + mf * 16 + ar) * TROW + kb) * 2);
#pragma unroll
            for (int mf = 0; mf < 4; mf++)
#pragma unroll
                for (int nb = 0; nb < 2; nb++)
#pragma unroll
                    for (int h = 0; h < 2; h++)
                        mma16816(acc[mf][nb * 2 + h], af[mf], bh[nb][h],
                                 bh[nb][h + 2]);
        }
    }
    __syncthreads();

    // epilogue: single-stage 128x132 fp32 smem, float4 stores
    float* stage = (float*)smem;
    {
        int r0r = wm * 64 + (lane >> 2);
        int c0c = wn * 32 + (lane & 3) * 2;
#pragma unroll
        for (int mf = 0; mf < 4; mf++)
#pragma unroll
            for (int nf = 0; nf < 4; nf++) {
                float* cc = acc[mf][nf];
                int rr = r0r + mf * 16;
                int ccol = c0c + nf * 8;
                stage[rr * 132 + ccol] = cc[0];
                stage[rr * 132 + ccol + 1] = cc[1];
                stage[(rr + 8) * 132 + ccol] = cc[2];
                stage[(rr + 8) * 132 + ccol + 1] = cc[3];
            }
    }
    __syncthreads();
#pragma unroll
    for (int j = 0; j < 16; j++) {
        int e = tid + 256 * j;
        int rr = e >> 5, c4 = e & 31;
        int gr = row0 + rr;
        if (gr < NN) {
            float4 v = *(const float4*)&stage[rr * 132 + c4 * 4];
            *(float4*)&C[(size_t)gr * HH + col0 + c4 * 4] = v;
        }
    }
}

// ---------------- GCN aggregation (+bias+relu) -> bf16 hi/lo split -------------
__global__ __launch_bounds__(256) void k_gcn_agg_bf(const float* __restrict__ T,
                                                    __nv_bfloat16* __restrict__ ah,
                                                    __nv_bfloat16* __restrict__ al,
                                                    const float* __restrict__ bias) {
    int n = blockIdx.x;
    float din = g_dinv[n];
    int s0 = g_rowstart[n], s1 = g_rowstart[n + 1];
    int f = threadIdx.x;
    float selfw = din * din;
    const float* rn = T + (size_t)n * HH;
    float a0 = rn[f] * selfw;
    float a1 = rn[f + 256] * selfw;
    float a2 = rn[f + 512] * selfw;
    for (int j = s0; j < s1; j++) {
        int s = g_csrsrc[j];
        float w = g_dinv[s] * din;
        const float* row = T + (size_t)s * HH;
        a0 += row[f] * w;
        a1 += row[f + 256] * w;
        a2 += row[f + 512] * w;
    }
    a0 = fmaxf(a0 + bias[f], 0.f);
    a1 = fmaxf(a1 + bias[f + 256], 0.f);
    a2 = fmaxf(a2 + bias[f + 512], 0.f);
    size_t base = (size_t)n * HH;
    float vv[3] = {a0, a1, a2};
#pragma unroll
    for (int c = 0; c < 3; c++) {
        __nv_bfloat16 h = __float2bfloat16(vv[c]);
        ah[base + f + c * 256] = h;
        al[base + f + c * 256] = __float2bfloat16(vv[c] - __bfloat162float(h));
    }
}

// ---------------- GAT alpha (per node, per head dot products) ----------------
__global__ void k_alpha(const float* __restrict__ Hg, const float* __restrict__ a_src,
                        const float* __restrict__ a_dst) {
    int gwarp = (blockIdx.x * blockDim.x + threadIdx.x) >> 5;
    int lane = threadIdx.x & 31;
    if (gwarp >= NN * NHD) return;
    int n = gwarp / NHD, h = gwarp % NHD;
    const float* row = Hg + (size_t)n * HH + h * HDD;
    float v0 = row[lane], v1 = row[lane + 32];
    float s = v0 * a_src[h * HDD + lane] + v1 * a_src[h * HDD + lane + 32];
    float d = v0 * a_dst[h * HDD + lane] + v1 * a_dst[h * HDD + lane + 32];
#pragma unroll
    for (int o = 16; o; o >>= 1) {
        s += __shfl_xor_sync(0xFFFFFFFFu, s, o);
        d += __shfl_xor_sync(0xFFFFFFFFu, d, o);
    }
    if (lane == 0) { g_as[gwarp] = s; g_ad[gwarp] = d; }
}

// ---------------- GAT aggregation (per-(edge,head) softmax weights in smem) ----
// mode 1: relu + write bf16 hi/lo (feeds next GEMM). mode 0: fp32 out, no relu.
#define CH 20
__global__ __launch_bounds__(256) void k_gat_agg(const float* __restrict__ Hg,
                                                 float* __restrict__ outf,
                                                 __nv_bfloat16* __restrict__ ah,
                                                 __nv_bfloat16* __restrict__ al,
                                                 const float* __restrict__ bias,
                                                 int mode) {
    __shared__ float sm[NHD], ssi[NHD], sself[NHD];
    __shared__ float swgt[CH][NHD];
    int n = blockIdx.x;
    int s0 = g_rowstart[n], s1 = g_rowstart[n + 1];
    int tid = threadIdx.x;

    if (tid < NHD) {
        float adn = g_ad[n * NHD + tid];
        float e_self = lrelu(g_as[n * NHD + tid] + adn);
        float m = e_self;
        for (int j = s0; j < s1; j++) {
            int s = g_csrsrc[j];
            float v = lrelu(g_as[s * NHD + tid] + adn);
            m = fmaxf(m, v);
        }
        float sum = __expf(e_self - m);
        for (int j = s0; j < s1; j++) {
            int s = g_csrsrc[j];
            sum += __expf(lrelu(g_as[s * NHD + tid] + adn) - m);
        }
        float inv = 1.0f / sum;
        sm[tid] = m;
        ssi[tid] = inv;
        sself[tid] = __expf(e_self - m) * inv;
    }
    __syncthreads();

    int h0 = tid >> 6;
    int h1 = (tid + 256) >> 6;
    int h2 = (tid + 512) >> 6;
    const float* rn = Hg + (size_t)n * HH;
    float acc0 = rn[tid] * sself[h0];
    float acc1 = rn[tid + 256] * sself[h1];
    float acc2v = rn[tid + 512] * sself[h2];

    for (int j0 = s0; j0 < s1; j0 += CH) {
        int cnt = min(CH, s1 - j0);
        if (tid < cnt * NHD) {
            int jj = tid / NHD, h = tid % NHD;
            int s = g_csrsrc[j0 + jj];
            swgt[jj][h] =
                __expf(lrelu(g_as[s * NHD + h] + g_ad[n * NHD + h]) - sm[h]) * ssi[h];
        }
        __syncthreads();
        for (int jj = 0; jj < cnt; jj++) {
            int s = g_csrsrc[j0 + jj];
            const float* row = Hg + (size_t)s * HH;
            acc0 += row[tid] * swgt[jj][h0];
            acc1 += row[tid + 256] * swgt[jj][h1];
            acc2v += row[tid + 512] * swgt[jj][h2];
        }
        __syncthreads();
    }

    float v0 = acc0 + bias[tid];
    float v1 = acc1 + bias[tid + 256];
    float v2 = acc2v + bias[tid + 512];
    size_t base = (size_t)n * HH;
    if (mode) {
        float vv[3] = {fmaxf(v0, 0.f), fmaxf(v1, 0.f), fmaxf(v2, 0.f)};
#pragma unroll
        for (int c = 0; c < 3; c++) {
            __nv_bfloat16 h = __float2bfloat16(vv[c]);
            ah[base + tid + c * 256] = h;
            al[base + tid + c * 256] = __float2bfloat16(vv[c] - __bfloat162float(h));
        }
    } else {
        outf[base + tid] = v0;
        outf[base + tid + 256] = v1;
        outf[base + tid + 512] = v2;
    }
}

// ---------------- global mean pool (sorted batch, binary search ranges) --------
__device__ __forceinline__ int lower_bound_batch(const int* b, int key) {
    int lo = 0, hi = NN;
    while (lo < hi) {
        int mid = (lo + hi) >> 1;
        if (b[mid] < key) lo = mid + 1; else hi = mid;
    }
    return lo;
}

__global__ void k_pool(const float* __restrict__ X, const int* __restrict__ batch) {
    int g = blockIdx.x / 12;
    int chunk = blockIdx.x % 12;
    int lo = lower_bound_batch(batch, g);
    int hi = lower_bound_batch(batch, g + 1);
    int f = chunk * 64 + threadIdx.x;
    float s = 0.f;
    for (int i = lo; i < hi; i++) s += X[(size_t)i * HH + f];
    float c = (float)((hi - lo) > 0 ? (hi - lo) : 1);
    g_pool[g * HH + f] = s / c;
}

// ---------------- classifier MLP ----------------
__global__ void k_mlp1(const float* __restrict__ wc1, const float* __restrict__ bc1) {
    __shared__ float sg[HH];
    int g = blockIdx.x;
    for (int i = threadIdx.x; i < HH; i += H2) sg[i] = g_pool[g * HH + i];
    __syncthreads();
    float acc = bc1[threadIdx.x];
    for (int k = 0; k < HH; k++) acc += sg[k] * wc1[k * H2 + threadIdx.x];
    g_zmlp[g * H2 + threadIdx.x] = fmaxf(acc, 0.f);
}

__global__ void k_mlp2(const float* __restrict__ wc2, const float* __restrict__ bc2,
                       float* __restrict__ out) {
    __shared__ float sz[H2];
    int g = blockIdx.x;
    for (int i = threadIdx.x; i < H2; i += 64) sz[i] = g_zmlp[g * H2 + i];
    __syncthreads();
    if (threadIdx.x < NCL) {
        float acc = bc2[threadIdx.x];
        for (int k = 0; k < H2; k++) acc += sz[k] * wc2[k * NCL + threadIdx.x];
        out[g * NCL + threadIdx.x] = acc;
    }
}

// ---------------- launch ----------------
extern "C" void kernel_launch(void* const* d_in, const int* in_sizes, int n_in,
                              void* d_out, int out_size) {
    const float* x    = (const float*)d_in[0];
    const int*   ei   = (const int*)d_in[1];
    const int*   batc = (const int*)d_in[2];
    const float* w1   = (const float*)d_in[3];
    const float* b1   = (const float*)d_in[4];
    const float* w2   = (const float*)d_in[5];
    const float* b2   = (const float*)d_in[6];
    const float* w3   = (const float*)d_in[7];
    const float* b3   = (const float*)d_in[8];
    const float* wg1  = (const float*)d_in[9];
    const float* as1  = (const float*)d_in[10];
    const float* ad1  = (const float*)d_in[11];
    const float* bg1  = (const float*)d_in[12];
    const float* wg2  = (const float*)d_in[13];
    const float* as2  = (const float*)d_in[14];
    const float* ad2  = (const float*)d_in[15];
    const float* bg2  = (const float*)d_in[16];
    const float* wc1  = (const float*)d_in[17];
    const float* bc1  = (const float*)d_in[18];
    const float* wc2  = (const float*)d_in[19];
    const float* bc2  = (const float*)d_in[20];
    float* out = (float*)d_out;

    float *bufA, *bufB;
    __nv_bfloat16 *Ah, *Al, *Wh, *Wl;
    cudaGetSymbolAddress((void**)&bufA, g_bufA);
    cudaGetSymbolAddress((void**)&bufB, g_bufB);
    cudaGetSymbolAddress((void**)&Ah, g_Ah);
    cudaGetSymbolAddress((void**)&Al, g_Al);
    cudaGetSymbolAddress((void**)&Wh, g_Wh);
    cudaGetSymbolAddress((void**)&Wl, g_Wl);

    cudaFuncSetAttribute(k_mma_gemm, cudaFuncAttributeMaxDynamicSharedMemorySize,
                         MMA_SMEM);

    dim3 tc_grid((NN + GBM - 1) / GBM, HH / GBN);   // x = row
    int splitW_blocks = (HH * HH) / 256;

    // CSR build
    k_zero_cnt<<<(NN + 255) / 256, 256>>>();
    k_count<<<(EE + 255) / 256, 256>>>(ei);
    k_scan<<<1, 1024>>>();
    k_dinv<<<(NN + 255) / 256, 256>>>();
    k_fill<<<(EE + 255) / 256, 256>>>(ei);

    // GCN layer 1 (fused via linearity): x -> Ah/Al
    k_gcn_l1<<<NN, 256>>>(x, w1, b1, Ah, Al);

    // GCN layer 2
    k_split_w<<<splitW_blocks, 256>>>(w2, Wh, Wl);
    k_mma_gemm<<<tc_grid, 256, MMA_SMEM>>>(Ah, Al, Wh, Wl, bufB);
    k_gcn_agg_bf<<<NN, 256>>>(bufB, Ah, Al, b2);

    // GCN layer 3
    k_split_w<<<splitW_blocks, 256>>>(w3, Wh, Wl);
    k_mma_gemm<<<tc_grid, 256, MMA_SMEM>>>(Ah, Al, Wh, Wl, bufB);
    k_gcn_agg_bf<<<NN, 256>>>(bufB, Ah, Al, b3);

    // GAT layer 1: gemm -> bufB (Hg) ; alpha ; agg -> Ah/Al (relu)
    k_split_w<<<splitW_blocks, 256>>>(wg1, Wh, Wl);
    k_mma_gemm<<<tc_grid, 256, MMA_SMEM>>>(Ah, Al, Wh, Wl, bufB);
    k_alpha<<<(NN * NHD * 32 + 255) / 256, 256>>>(bufB, as1, ad1);
    k_gat_agg<<<NN, 256>>>(bufB, nullptr, Ah, Al, bg1, 1);

    // GAT layer 2: gemm -> bufB ; alpha ; agg -> bufA (fp32, no relu)
    k_split_w<<<splitW_blocks, 256>>>(wg2, Wh, Wl);
    k_mma_gemm<<<tc_grid, 256, MMA_SMEM>>>(Ah, Al, Wh, Wl, bufB);
    k_alpha<<<(NN * NHD * 32 + 255) / 256, 256>>>(bufB, as2, ad2);
    k_gat_agg<<<NN, 256>>>(bufB, bufA, nullptr, nullptr, bg2, 0);

    // pool + MLP
    k_pool<<<NGR * 12, 64>>>(bufA, batc);
    k_mlp1<<<NGR, H2>>>(wc1, bc1);
    k_mlp2<<<NGR, 64>>>(wc2, bc2, out);
}

// round 13
// speedup vs baseline: 2.3430x; 1.3247x over previous
#include <cuda_runtime.h>
#include <cuda_bf16.h>
#include <cuda_fp16.h>
#include <math.h>
#include <stdint.h>

#define NN 50000
#define EE 100000
#define HH 768
#define NHD 12
#define HDD 64
#define NGR 64
#define NCL 10
#define H2 384
#define WSCALE 16.0f
#define WUNSCALE 0.0625f

// ---------------- scratch (static device globals; no allocation) ----------------
__device__ float g_bufA[(size_t)NN * HH];
__device__ float g_bufB[(size_t)NN * HH];
__device__ __half g_Ah[(size_t)NN * HH];
__device__ __half g_Wh[(size_t)HH * HH];   // transposed: [N=768][K=768], x16
__device__ __half g_Wl[(size_t)HH * HH];
__device__ float g_dinv[NN];
__device__ int   g_cnt[NN];
__device__ int   g_rowstart[NN + 1];
__device__ int   g_cursor[NN];
__device__ int   g_csrsrc[EE];
__device__ float g_as[NN * NHD];
__device__ float g_ad[NN * NHD];
__device__ float g_pool[NGR * HH];
__device__ float g_zmlp[NGR * H2];

__device__ __forceinline__ float lrelu(float x) { return x > 0.f ? x : 0.2f * x; }

// ---------------- CSR build ----------------
__global__ void k_zero_cnt() {
    int i = blockIdx.x * blockDim.x + threadIdx.x;
    if (i < NN) g_cnt[i] = 0;
}

__global__ void k_count(const int* __restrict__ ei) {
    int e = blockIdx.x * blockDim.x + threadIdx.x;
    if (e < EE) atomicAdd(&g_cnt[ei[EE + e]], 1);
}

__global__ void k_scan() {
    __shared__ int sh[1024];
    int tid = threadIdx.x;
    int off = 0;
    for (int base = 0; base < NN; base += 1024) {
        int i = base + tid;
        int v = (i < NN) ? g_cnt[i] : 0;
        sh[tid] = v;
        __syncthreads();
        for (int s = 1; s < 1024; s <<= 1) {
            int t = (tid >= s) ? sh[tid - s] : 0;
            __syncthreads();
            sh[tid] += t;
            __syncthreads();
        }
        if (i < NN) {
            int excl = off + sh[tid] - v;
            g_rowstart[i] = excl;
            g_cursor[i] = excl;
        }
        int tot = sh[1023];
        __syncthreads();
        off += tot;
    }
    if (tid == 0) g_rowstart[NN] = off;
}

__global__ void k_dinv() {
    int i = blockIdx.x * blockDim.x + threadIdx.x;
    if (i < NN) g_dinv[i] = rsqrtf((float)(g_cnt[i] + 1));
}

__global__ void k_fill(const int* __restrict__ ei) {
    int e = blockIdx.x * blockDim.x + threadIdx.x;
    if (e < EE) {
        int s = ei[e];
        int d = ei[EE + e];
        int pos = atomicAdd(&g_cursor[d], 1);
        g_csrsrc[pos] = s;
    }
}

// ---------------- fused GCN layer 1 (linearity: Agg(x@W) == Agg(x)@W) ---------
__global__ __launch_bounds__(256) void k_gcn_l1(const float* __restrict__ x,
                                                const float* __restrict__ w1,
                                                const float* __restrict__ b1,
                                                __half* __restrict__ ah) {
    __shared__ float xb[3];
    int n = blockIdx.x;
    int tid = threadIdx.x;
    if (tid < 3) {
        float din = g_dinv[n];
        float acc = x[n * 3 + tid] * din * din;
        int s0 = g_rowstart[n], s1 = g_rowstart[n + 1];
        for (int j = s0; j < s1; j++) {
            int s = g_csrsrc[j];
            acc += x[s * 3 + tid] * g_dinv[s] * din;
        }
        xb[tid] = acc;
    }
    __syncthreads();
    float x0 = xb[0], x1 = xb[1], x2 = xb[2];
    size_t base = (size_t)n * HH;
#pragma unroll
    for (int c = 0; c < 3; c++) {
        int f = tid + c * 256;
        float v = x0 * w1[f] + x1 * w1[HH + f] + x2 * w1[2 * HH + f] + b1[f];
        ah[base + f] = __float2half(fmaxf(v, 0.f));
    }
}

// ---------------- weight transpose + split (fp16, scaled x16) -----------------
__global__ void k_split_w(const float* __restrict__ w,
                          __half* __restrict__ th,
                          __half* __restrict__ tl) {
    int idx = blockIdx.x * 256 + threadIdx.x;
    int n = idx / HH, k = idx % HH;
    float v = w[(size_t)k * HH + n] * WSCALE;
    __half h = __float2half(v);
    th[idx] = h;
    tl[idx] = __float2half(v - __half2float(h));
}

// ---------------- mma.sync GEMM: C[M,768] = A[M,768] @ W[768,768] --------------
// A fp16 [M,768]; W transposed, scaled x16, split hi/lo fp16 [768(N),768(K)].
// acc += Ah*Wh + Ah*Wl  (fp32 accumulators); epilogue scales by 1/16.
#define GBM 128
#define GBN 128
#define GBK 32
#define KIT (HH / GBK)          // 24
#define TROW 40                 // padded row (fp16 elems): 80 bytes
#define TSZ (GBM * TROW)        // 5120 fp16 elems per tile
#define STGB (3 * TSZ * 2)      // 30720 bytes per stage: [A][Bh][Bl]
#define MMA_SMEM 67584          // max(2*STGB=61440, epilogue 128*132*4=67584)

__device__ __forceinline__ void ldsm4(uint32_t* r, uint32_t addr) {
    asm volatile("ldmatrix.sync.aligned.m8n8.x4.shared.b16 {%0,%1,%2,%3}, [%4];"
                 : "=r"(r[0]), "=r"(r[1]), "=r"(r[2]), "=r"(r[3]) : "r"(addr));
}
__device__ __forceinline__ void mma16816(float* c, const uint32_t* a, uint32_t b0,
                                         uint32_t b1) {
    asm volatile(
        "mma.sync.aligned.m16n8k16.row.col.f32.f16.f16.f32 "
        "{%0,%1,%2,%3}, {%4,%5,%6,%7}, {%8,%9}, {%0,%1,%2,%3};"
        : "+f"(c[0]), "+f"(c[1]), "+f"(c[2]), "+f"(c[3])
        : "r"(a[0]), "r"(a[1]), "r"(a[2]), "r"(a[3]), "r"(b0), "r"(b1));
}
__device__ __forceinline__ void cpa16(uint32_t dst, const void* src, int sz) {
    asm volatile("cp.async.ca.shared.global [%0], [%1], 16, %2;"
                 :: "r"(dst), "l"(src), "r"(sz) : "memory");
}

__global__ __launch_bounds__(256) void k_mma_gemm(const __half* __restrict__ A,
                                                  const __half* __restrict__ Bh,
                                                  const __half* __restrict__ Bl,
                                                  float* __restrict__ C) {
    extern __shared__ char smem[];
    uint32_t sb;
    asm("{ .reg .u64 t; cvta.to.shared.u64 t, %1; cvt.u32.u64 %0, t; }"
        : "=r"(sb) : "l"(smem));
    int tid = threadIdx.x;
    int lane = tid & 31, wid = tid >> 5;
    int wm = wid & 1, wn = wid >> 1;
    int row0 = blockIdx.x * GBM;
    int col0 = blockIdx.y * GBN;

    float acc[4][4][4];
#pragma unroll
    for (int i = 0; i < 4; i++)
#pragma unroll
        for (int j = 0; j < 4; j++)
#pragma unroll
            for (int q = 0; q < 4; q++) acc[i][j][q] = 0.f;

    int vr = tid >> 2;          // row handled by this thread's vectors
    int vc = (tid & 3) * 8;     // fp16 col within 32-wide chunk
    int grA = row0 + vr;
    int okA = (grA < NN) ? 16 : 0;
    const char* pA0 = (const char*)(A + (size_t)(okA ? grA : 0) * HH + vc);
    const char* pBh0 = (const char*)(Bh + (size_t)(col0 + vr) * HH + vc);
    const char* pBl0 = (const char*)(Bl + (size_t)(col0 + vr) * HH + vc);
    int grA2 = row0 + vr + 64;
    int okA2 = (grA2 < NN) ? 16 : 0;
    const char* pA1 = (const char*)(A + (size_t)(okA2 ? grA2 : 0) * HH + vc);
    const char* pBh1 = (const char*)(Bh + (size_t)(col0 + vr + 64) * HH + vc);
    const char* pBl1 = (const char*)(Bl + (size_t)(col0 + vr + 64) * HH + vc);
    uint32_t d0 = sb + (vr * TROW + vc) * 2;
    uint32_t d1 = sb + ((vr + 64) * TROW + vc) * 2;

#define LOAD_TILES(buf, kbyte)                                                  \
    do {                                                                        \
        uint32_t bo = (buf) * STGB;                                             \
        cpa16(bo + d0 + 0 * TSZ * 2, pA0 + (kbyte), okA);                       \
        cpa16(bo + d1 + 0 * TSZ * 2, pA1 + (kbyte), okA2);                      \
        cpa16(bo + d0 + 1 * TSZ * 2, pBh0 + (kbyte), 16);                       \
        cpa16(bo + d1 + 1 * TSZ * 2, pBh1 + (kbyte), 16);                       \
        cpa16(bo + d0 + 2 * TSZ * 2, pBl0 + (kbyte), 16);                       \
        cpa16(bo + d1 + 2 * TSZ * 2, pBl1 + (kbyte), 16);                       \
        asm volatile("cp.async.commit_group;" ::: "memory");                    \
    } while (0)

    LOAD_TILES(0, 0);

    int ar = lane & 15;
    int kc = (lane >> 4) * 8;

    for (int kt = 0; kt < KIT; kt++) {
        asm volatile("cp.async.wait_group 0;" ::: "memory");
        __syncthreads();
        if (kt + 1 < KIT) LOAD_TILES((kt + 1) & 1, (kt + 1) * GBK * 2);

        uint32_t tb = sb + (kt & 1) * STGB;
#pragma unroll
        for (int ks = 0; ks < 2; ks++) {
            int kb = ks * 16 + kc;
            uint32_t bh[2][4], bl_[2][4], af[4][4];
#pragma unroll
            for (int nb = 0; nb < 2; nb++) {
                uint32_t addr =
                    tb + 1 * TSZ * 2 + ((wn * 32 + nb * 16 + ar) * TROW + kb) * 2;
                ldsm4(bh[nb], addr);
                ldsm4(bl_[nb], addr + TSZ * 2);
            }
#pragma unroll
            for (int mf = 0; mf < 4; mf++)
                ldsm4(af[mf], tb + ((wm * 64 + mf * 16 + ar) * TROW + kb) * 2);
#pragma unroll
            for (int mf = 0; mf < 4; mf++)
#pragma unroll
                for (int nb = 0; nb < 2; nb++)
#pragma unroll
                    for (int h = 0; h < 2; h++) {
                        float* cc = acc[mf][nb * 2 + h];
                        mma16816(cc, af[mf], bh[nb][h], bh[nb][h + 2]);
                        mma16816(cc, af[mf], bl_[nb][h], bl_[nb][h + 2]);
                    }
        }
    }
    __syncthreads();

    // epilogue: single-stage 128x132 fp32 smem (scaled by 1/16), float4 stores
    float* stage = (float*)smem;
    {
        int r0r = wm * 64 + (lane >> 2);
        int c0c = wn * 32 + (lane & 3) * 2;
#pragma unroll
        for (int mf = 0; mf < 4; mf++)
#pragma unroll
            for (int nf = 0; nf < 4; nf++) {
                float* cc = acc[mf][nf];
                int rr = r0r + mf * 16;
                int ccol = c0c + nf * 8;
                stage[rr * 132 + ccol] = cc[0] * WUNSCALE;
                stage[rr * 132 + ccol + 1] = cc[1] * WUNSCALE;
                stage[(rr + 8) * 132 + ccol] = cc[2] * WUNSCALE;
                stage[(rr + 8) * 132 + ccol + 1] = cc[3] * WUNSCALE;
            }
    }
    __syncthreads();
#pragma unroll
    for (int j = 0; j < 16; j++) {
        int e = tid + 256 * j;
        int rr = e >> 5, c4 = e & 31;
        int gr = row0 + rr;
        if (gr < NN) {
            float4 v = *(const float4*)&stage[rr * 132 + c4 * 4];
            *(float4*)&C[(size_t)gr * HH + col0 + c4 * 4] = v;
        }
    }
}

// ---------------- GCN aggregation (+bias+relu) -> fp16 ------------------------
__global__ __launch_bounds__(256) void k_gcn_agg_h(const float* __restrict__ T,
                                                   __half* __restrict__ ah,
                                                   const float* __restrict__ bias) {
    int n = blockIdx.x;
    float din = g_dinv[n];
    int s0 = g_rowstart[n], s1 = g_rowstart[n + 1];
    int f = threadIdx.x;
    float selfw = din * din;
    const float* rn = T + (size_t)n * HH;
    float a0 = rn[f] * selfw;
    float a1 = rn[f + 256] * selfw;
    float a2 = rn[f + 512] * selfw;
    for (int j = s0; j < s1; j++) {
        int s = g_csrsrc[j];
        float w = g_dinv[s] * din;
        const float* row = T + (size_t)s * HH;
        a0 += row[f] * w;
        a1 += row[f + 256] * w;
        a2 += row[f + 512] * w;
    }
    size_t base = (size_t)n * HH;
    ah[base + f] = __float2half(fmaxf(a0 + bias[f], 0.f));
    ah[base + f + 256] = __float2half(fmaxf(a1 + bias[f + 256], 0.f));
    ah[base + f + 512] = __float2half(fmaxf(a2 + bias[f + 512], 0.f));
}

// ---------------- GAT alpha (per node, per head dot products) ----------------
__global__ void k_alpha(const float* __restrict__ Hg, const float* __restrict__ a_src,
                        const float* __restrict__ a_dst) {
    int gwarp = (blockIdx.x * blockDim.x + threadIdx.x) >> 5;
    int lane = threadIdx.x & 31;
    if (gwarp >= NN * NHD) return;
    int n = gwarp / NHD, h = gwarp % NHD;
    const float* row = Hg + (size_t)n * HH + h * HDD;
    float v0 = row[lane], v1 = row[lane + 32];
    float s = v0 * a_src[h * HDD + lane] + v1 * a_src[h * HDD + lane + 32];
    float d = v0 * a_dst[h * HDD + lane] + v1 * a_dst[h * HDD + lane + 32];
#pragma unroll
    for (int o = 16; o; o >>= 1) {
        s += __shfl_xor_sync(0xFFFFFFFFu, s, o);
        d += __shfl_xor_sync(0xFFFFFFFFu, d, o);
    }
    if (lane == 0) { g_as[gwarp] = s; g_ad[gwarp] = d; }
}

// ---------------- GAT aggregation (per-(edge,head) softmax weights in smem) ----
// mode 1: relu + write fp16 (feeds next GEMM). mode 0: fp32 out, no relu.
#define CH 20
__global__ __launch_bounds__(256) void k_gat_agg(const float* __restrict__ Hg,
                                                 float* __restrict__ outf,
                                                 __half* __restrict__ ah,
                                                 const float* __restrict__ bias,
                                                 int mode) {
    __shared__ float sm[NHD], ssi[NHD], sself[NHD];
    __shared__ float swgt[CH][NHD];
    int n = blockIdx.x;
    int s0 = g_rowstart[n], s1 = g_rowstart[n + 1];
    int tid = threadIdx.x;

    if (tid < NHD) {
        float adn = g_ad[n * NHD + tid];
        float e_self = lrelu(g_as[n * NHD + tid] + adn);
        float m = e_self;
        for (int j = s0; j < s1; j++) {
            int s = g_csrsrc[j];
            float v = lrelu(g_as[s * NHD + tid] + adn);
            m = fmaxf(m, v);
        }
        float sum = __expf(e_self - m);
        for (int j = s0; j < s1; j++) {
            int s = g_csrsrc[j];
            sum += __expf(lrelu(g_as[s * NHD + tid] + adn) - m);
        }
        float inv = 1.0f / sum;
        sm[tid] = m;
        ssi[tid] = inv;
        sself[tid] = __expf(e_self - m) * inv;
    }
    __syncthreads();

    int h0 = tid >> 6;
    int h1 = (tid + 256) >> 6;
    int h2 = (tid + 512) >> 6;
    const float* rn = Hg + (size_t)n * HH;
    float acc0 = rn[tid] * sself[h0];
    float acc1 = rn[tid + 256] * sself[h1];
    float acc2v = rn[tid + 512] * sself[h2];

    for (int j0 = s0; j0 < s1; j0 += CH) {
        int cnt = min(CH, s1 - j0);
        if (tid < cnt * NHD) {
            int jj = tid / NHD, h = tid % NHD;
            int s = g_csrsrc[j0 + jj];
            swgt[jj][h] =
                __expf(lrelu(g_as[s * NHD + h] + g_ad[n * NHD + h]) - sm[h]) * ssi[h];
        }
        __syncthreads();
        for (int jj = 0; jj < cnt; jj++) {
            int s = g_csrsrc[j0 + jj];
            const float* row = Hg + (size_t)s * HH;
            acc0 += row[tid] * swgt[jj][h0];
            acc1 += row[tid + 256] * swgt[jj][h1];
            acc2v += row[tid + 512] * swgt[jj][h2];
        }
        __syncthreads();
    }

    float v0 = acc0 + bias[tid];
    float v1 = acc1 + bias[tid + 256];
    float v2 = acc2v + bias[tid + 512];
    size_t base = (size_t)n * HH;
    if (mode) {
        ah[base + tid] = __float2half(fmaxf(v0, 0.f));
        ah[base + tid + 256] = __float2half(fmaxf(v1, 0.f));
        ah[base + tid + 512] = __float2half(fmaxf(v2, 0.f));
    } else {
        outf[base + tid] = v0;
        outf[base + tid + 256] = v1;
        outf[base + tid + 512] = v2;
    }
}

// ---------------- global mean pool (sorted batch, binary search ranges) --------
__device__ __forceinline__ int lower_bound_batch(const int* b, int key) {
    int lo = 0, hi = NN;
    while (lo < hi) {
        int mid = (lo + hi) >> 1;
        if (b[mid] < key) lo = mid + 1; else hi = mid;
    }
    return lo;
}

__global__ void k_pool(const float* __restrict__ X, const int* __restrict__ batch) {
    int g = blockIdx.x / 12;
    int chunk = blockIdx.x % 12;
    int lo = lower_bound_batch(batch, g);
    int hi = lower_bound_batch(batch, g + 1);
    int f = chunk * 64 + threadIdx.x;
    float s = 0.f;
    for (int i = lo; i < hi; i++) s += X[(size_t)i * HH + f];
    float c = (float)((hi - lo) > 0 ? (hi - lo) : 1);
    g_pool[g * HH + f] = s / c;
}

// ---------------- classifier MLP ----------------
__global__ void k_mlp1(const float* __restrict__ wc1, const float* __restrict__ bc1) {
    __shared__ float sg[HH];
    int g = blockIdx.x;
    for (int i = threadIdx.x; i < HH; i += H2) sg[i] = g_pool[g * HH + i];
    __syncthreads();
    float acc = bc1[threadIdx.x];
    for (int k = 0; k < HH; k++) acc += sg[k] * wc1[k * H2 + threadIdx.x];
    g_zmlp[g * H2 + threadIdx.x] = fmaxf(acc, 0.f);
}

__global__ void k_mlp2(const float* __restrict__ wc2, const float* __restrict__ bc2,
                       float* __restrict__ out) {
    __shared__ float sz[H2];
    int g = blockIdx.x;
    for (int i = threadIdx.x; i < H2; i += 64) sz[i] = g_zmlp[g * H2 + i];
    __syncthreads();
    if (threadIdx.x < NCL) {
        float acc = bc2[threadIdx.x];
        for (int k = 0; k < H2; k++) acc += sz[k] * wc2[k * NCL + threadIdx.x];
        out[g * NCL + threadIdx.x] = acc;
    }
}

// ---------------- launch ----------------
extern "C" void kernel_launch(void* const* d_in, const int* in_sizes, int n_in,
                              void* d_out, int out_size) {
    const float* x    = (const float*)d_in[0];
    const int*   ei   = (const int*)d_in[1];
    const int*   batc = (const int*)d_in[2];
    const float* w1   = (const float*)d_in[3];
    const float* b1   = (const float*)d_in[4];
    const float* w2   = (const float*)d_in[5];
    const float* b2   = (const float*)d_in[6];
    const float* w3   = (const float*)d_in[7];
    const float* b3   = (const float*)d_in[8];
    const float* wg1  = (const float*)d_in[9];
    const float* as1  = (const float*)d_in[10];
    const float* ad1  = (const float*)d_in[11];
    const float* bg1  = (const float*)d_in[12];
    const float* wg2  = (const float*)d_in[13];
    const float* as2  = (const float*)d_in[14];
    const float* ad2  = (const float*)d_in[15];
    const float* bg2  = (const float*)d_in[16];
    const float* wc1  = (const float*)d_in[17];
    const float* bc1  = (const float*)d_in[18];
    const float* wc2  = (const float*)d_in[19];
    const float* bc2  = (const float*)d_in[20];
    float* out = (float*)d_out;

    float *bufA, *bufB;
    __half *Ah, *Wh, *Wl;
    cudaGetSymbolAddress((void**)&bufA, g_bufA);
    cudaGetSymbolAddress((void**)&bufB, g_bufB);
    cudaGetSymbolAddress((void**)&Ah, g_Ah);
    cudaGetSymbolAddress((void**)&Wh, g_Wh);
    cudaGetSymbolAddress((void**)&Wl, g_Wl);

    cudaFuncSetAttribute(k_mma_gemm, cudaFuncAttributeMaxDynamicSharedMemorySize,
                         MMA_SMEM);

    dim3 tc_grid((NN + GBM - 1) / GBM, HH / GBN);   // x = row
    int splitW_blocks = (HH * HH) / 256;

    // CSR build
    k_zero_cnt<<<(NN + 255) / 256, 256>>>();
    k_count<<<(EE + 255) / 256, 256>>>(ei);
    k_scan<<<1, 1024>>>();
    k_dinv<<<(NN + 255) / 256, 256>>>();
    k_fill<<<(EE + 255) / 256, 256>>>(ei);

    // GCN layer 1 (fused via linearity): x -> Ah
    k_gcn_l1<<<NN, 256>>>(x, w1, b1, Ah);

    // GCN layer 2
    k_split_w<<<splitW_blocks, 256>>>(w2, Wh, Wl);
    k_mma_gemm<<<tc_grid, 256, MMA_SMEM>>>(Ah, Wh, Wl, bufB);
    k_gcn_agg_h<<<NN, 256>>>(bufB, Ah, b2);

    // GCN layer 3
    k_split_w<<<splitW_blocks, 256>>>(w3, Wh, Wl);
    k_mma_gemm<<<tc_grid, 256, MMA_SMEM>>>(Ah, Wh, Wl, bufB);
    k_gcn_agg_h<<<NN, 256>>>(bufB, Ah, b3);

    // GAT layer 1: gemm -> bufB (Hg) ; alpha ; agg -> Ah (relu)
    k_split_w<<<splitW_blocks, 256>>>(wg1, Wh, Wl);
    k_mma_gemm<<<tc_grid, 256, MMA_SMEM>>>(Ah, Wh, Wl, bufB);
    k_alpha<<<(NN * NHD * 32 + 255) / 256, 256>>>(bufB, as1, ad1);
    k_gat_agg<<<NN, 256>>>(bufB, nullptr, Ah, bg1, 1);

    // GAT layer 2: gemm -> bufB ; alpha ; agg -> bufA (fp32, no relu)
    k_split_w<<<splitW_blocks, 256>>>(wg2, Wh, Wl);
    k_mma_gemm<<<tc_grid, 256, MMA_SMEM>>>(Ah, Wh, Wl, bufB);
    k_alpha<<<(NN * NHD * 32 + 255) / 256, 256>>>(bufB, as2, ad2);
    k_gat_agg<<<NN, 256>>>(bufB, bufA, nullptr, bg2, 0);

    // pool + MLP
    k_pool<<<NGR * 12, 64>>>(bufA, batc);
    k_mlp1<<<NGR, H2>>>(wc1, bc1);
    k_mlp2<<<NGR, 64>>>(wc2, bc2, out);
}

// round 14
// speedup vs baseline: 3.3447x; 1.4276x over previous
#include <cuda_runtime.h>
#include <cuda_bf16.h>
#include <cuda_fp16.h>
#include <math.h>
#include <stdint.h>

#define NN 50000
#define EE 100000
#define HH 768
#define NHD 12
#define HDD 64
#define NGR 64
#define NCL 10
#define H2 384

// ---------------- scratch (static device globals; no allocation) ----------------
__device__ float g_bufA[(size_t)NN * HH];
__device__ __half g_bufB[(size_t)NN * HH];
__device__ __half g_Ah[(size_t)NN * HH];
__device__ __half g_Wh[(size_t)HH * HH];   // transposed: [N=768][K=768]
__device__ float g_dinv[NN];
__device__ int   g_cnt[NN];
__device__ int   g_rowstart[NN + 1];
__device__ int   g_cursor[NN];
__device__ int   g_csrsrc[EE];
__device__ float g_as[NN * NHD];
__device__ float g_ad[NN * NHD];
__device__ float g_pool[NGR * HH];
__device__ float g_zmlp[NGR * H2];

__device__ __forceinline__ float lrelu(float x) { return x > 0.f ? x : 0.2f * x; }

// ---------------- CSR build ----------------
__global__ void k_zero_cnt() {
    int i = blockIdx.x * blockDim.x + threadIdx.x;
    if (i < NN) g_cnt[i] = 0;
}

__global__ void k_count(const int* __restrict__ ei) {
    int e = blockIdx.x * blockDim.x + threadIdx.x;
    if (e < EE) atomicAdd(&g_cnt[ei[EE + e]], 1);
}

__global__ void k_scan() {
    __shared__ int sh[1024];
    int tid = threadIdx.x;
    int off = 0;
    for (int base = 0; base < NN; base += 1024) {
        int i = base + tid;
        int v = (i < NN) ? g_cnt[i] : 0;
        sh[tid] = v;
        __syncthreads();
        for (int s = 1; s < 1024; s <<= 1) {
            int t = (tid >= s) ? sh[tid - s] : 0;
            __syncthreads();
            sh[tid] += t;
            __syncthreads();
        }
        if (i < NN) {
            int excl = off + sh[tid] - v;
            g_rowstart[i] = excl;
            g_cursor[i] = excl;
        }
        int tot = sh[1023];
        __syncthreads();
        off += tot;
    }
    if (tid == 0) g_rowstart[NN] = off;
}

__global__ void k_dinv() {
    int i = blockIdx.x * blockDim.x + threadIdx.x;
    if (i < NN) g_dinv[i] = rsqrtf((float)(g_cnt[i] + 1));
}

__global__ void k_fill(const int* __restrict__ ei) {
    int e = blockIdx.x * blockDim.x + threadIdx.x;
    if (e < EE) {
        int s = ei[e];
        int d = ei[EE + e];
        int pos = atomicAdd(&g_cursor[d], 1);
        g_csrsrc[pos] = s;
    }
}

// ---------------- fused GCN layer 1 (linearity: Agg(x@W) == Agg(x)@W) ---------
__global__ __launch_bounds__(256) void k_gcn_l1(const float* __restrict__ x,
                                                const float* __restrict__ w1,
                                                const float* __restrict__ b1,
                                                __half* __restrict__ ah) {
    __shared__ float xb[3];
    int n = blockIdx.x;
    int tid = threadIdx.x;
    if (tid < 3) {
        float din = g_dinv[n];
        float acc = x[n * 3 + tid] * din * din;
        int s0 = g_rowstart[n], s1 = g_rowstart[n + 1];
        for (int j = s0; j < s1; j++) {
            int s = g_csrsrc[j];
            acc += x[s * 3 + tid] * g_dinv[s] * din;
        }
        xb[tid] = acc;
    }
    __syncthreads();
    float x0 = xb[0], x1 = xb[1], x2 = xb[2];
    size_t base = (size_t)n * HH;
#pragma unroll
    for (int c = 0; c < 3; c++) {
        int f = tid + c * 256;
        float v = x0 * w1[f] + x1 * w1[HH + f] + x2 * w1[2 * HH + f] + b1[f];
        ah[base + f] = __float2half(fmaxf(v, 0.f));
    }
}

// ---------------- weight transpose + convert (fp16) ----------------
__global__ void k_split_w(const float* __restrict__ w,
                          __half* __restrict__ th) {
    int idx = blockIdx.x * 256 + threadIdx.x;
    int n = idx / HH, k = idx % HH;
    th[idx] = __float2half(w[(size_t)k * HH + n]);
}

// ---------------- mma.sync GEMM: C[M,768] = A[M,768] @ W[768,768] --------------
// A fp16 [M,768]; W transposed fp16 [768(N),768(K)]. Single-pass, fp32 accum.
// C written as fp16.
#define GBM 128
#define GBN 128
#define GBK 32
#define KIT (HH / GBK)          // 24
#define TROW 40                 // padded row (fp16 elems): 80 bytes
#define TSZ (GBM * TROW)        // 5120 fp16 elems per tile
#define STGB (2 * TSZ * 2)      // 20480 bytes per stage: [A][Bh]
#define MMA_SMEM 40960          // max(2*STGB=40960, epilogue 128*136*2=34816)

__device__ __forceinline__ void ldsm4(uint32_t* r, uint32_t addr) {
    asm volatile("ldmatrix.sync.aligned.m8n8.x4.shared.b16 {%0,%1,%2,%3}, [%4];"
                 : "=r"(r[0]), "=r"(r[1]), "=r"(r[2]), "=r"(r[3]) : "r"(addr));
}
__device__ __forceinline__ void mma16816(float* c, const uint32_t* a, uint32_t b0,
                                         uint32_t b1) {
    asm volatile(
        "mma.sync.aligned.m16n8k16.row.col.f32.f16.f16.f32 "
        "{%0,%1,%2,%3}, {%4,%5,%6,%7}, {%8,%9}, {%0,%1,%2,%3};"
        : "+f"(c[0]), "+f"(c[1]), "+f"(c[2]), "+f"(c[3])
        : "r"(a[0]), "r"(a[1]), "r"(a[2]), "r"(a[3]), "r"(b0), "r"(b1));
}
__device__ __forceinline__ void cpa16(uint32_t dst, const void* src, int sz) {
    asm volatile("cp.async.ca.shared.global [%0], [%1], 16, %2;"
                 :: "r"(dst), "l"(src), "r"(sz) : "memory");
}

__global__ __launch_bounds__(256) void k_mma_gemm(const __half* __restrict__ A,
                                                  const __half* __restrict__ Bh,
                                                  __half* __restrict__ C) {
    extern __shared__ char smem[];
    uint32_t sb;
    asm("{ .reg .u64 t; cvta.to.shared.u64 t, %1; cvt.u32.u64 %0, t; }"
        : "=r"(sb) : "l"(smem));
    int tid = threadIdx.x;
    int lane = tid & 31, wid = tid >> 5;
    int wm = wid & 1, wn = wid >> 1;
    int row0 = blockIdx.x * GBM;
    int col0 = blockIdx.y * GBN;

    float acc[4][4][4];
#pragma unroll
    for (int i = 0; i < 4; i++)
#pragma unroll
        for (int j = 0; j < 4; j++)
#pragma unroll
            for (int q = 0; q < 4; q++) acc[i][j][q] = 0.f;

    int vr = tid >> 2;          // row handled by this thread's vectors
    int vc = (tid & 3) * 8;     // fp16 col within 32-wide chunk
    int grA = row0 + vr;
    int okA = (grA < NN) ? 16 : 0;
    const char* pA0 = (const char*)(A + (size_t)(okA ? grA : 0) * HH + vc);
    const char* pBh0 = (const char*)(Bh + (size_t)(col0 + vr) * HH + vc);
    int grA2 = row0 + vr + 64;
    int okA2 = (grA2 < NN) ? 16 : 0;
    const char* pA1 = (const char*)(A + (size_t)(okA2 ? grA2 : 0) * HH + vc);
    const char* pBh1 = (const char*)(Bh + (size_t)(col0 + vr + 64) * HH + vc);
    uint32_t d0 = sb + (vr * TROW + vc) * 2;
    uint32_t d1 = sb + ((vr + 64) * TROW + vc) * 2;

#define LOAD_TILES(buf, kbyte)                                                  \
    do {                                                                        \
        uint32_t bo = (buf) * STGB;                                             \
        cpa16(bo + d0 + 0 * TSZ * 2, pA0 + (kbyte), okA);                       \
        cpa16(bo + d1 + 0 * TSZ * 2, pA1 + (kbyte), okA2);                      \
        cpa16(bo + d0 + 1 * TSZ * 2, pBh0 + (kbyte), 16);                       \
        cpa16(bo + d1 + 1 * TSZ * 2, pBh1 + (kbyte), 16);                       \
        asm volatile("cp.async.commit_group;" ::: "memory");                    \
    } while (0)

    LOAD_TILES(0, 0);

    int ar = lane & 15;
    int kc = (lane >> 4) * 8;

    for (int kt = 0; kt < KIT; kt++) {
        asm volatile("cp.async.wait_group 0;" ::: "memory");
        __syncthreads();
        if (kt + 1 < KIT) LOAD_TILES((kt + 1) & 1, (kt + 1) * GBK * 2);

        uint32_t tb = sb + (kt & 1) * STGB;
#pragma unroll
        for (int ks = 0; ks < 2; ks++) {
            int kb = ks * 16 + kc;
            uint32_t bh[2][4], af[4][4];
#pragma unroll
            for (int nb = 0; nb < 2; nb++)
                ldsm4(bh[nb],
                      tb + 1 * TSZ * 2 + ((wn * 32 + nb * 16 + ar) * TROW + kb) * 2);
#pragma unroll
            for (int mf = 0; mf < 4; mf++)
                ldsm4(af[mf], tb + ((wm * 64 + mf * 16 + ar) * TROW + kb) * 2);
#pragma unroll
            for (int mf = 0; mf < 4; mf++)
#pragma unroll
                for (int nb = 0; nb < 2; nb++)
#pragma unroll
                    for (int h = 0; h < 2; h++)
                        mma16816(acc[mf][nb * 2 + h], af[mf], bh[nb][h],
                                 bh[nb][h + 2]);
        }
    }
    __syncthreads();

    // epilogue: single-stage 128x136 fp16 smem, uint4 (8-half) stores
    __half* stage = (__half*)smem;
    {
        int r0r = wm * 64 + (lane >> 2);
        int c0c = wn * 32 + (lane & 3) * 2;
#pragma unroll
        for (int mf = 0; mf < 4; mf++)
#pragma unroll
            for (int nf = 0; nf < 4; nf++) {
                float* cc = acc[mf][nf];
                int rr = r0r + mf * 16;
                int ccol = c0c + nf * 8;
                stage[rr * 136 + ccol] = __float2half(cc[0]);
                stage[rr * 136 + ccol + 1] = __float2half(cc[1]);
                stage[(rr + 8) * 136 + ccol] = __float2half(cc[2]);
                stage[(rr + 8) * 136 + ccol + 1] = __float2half(cc[3]);
            }
    }
    __syncthreads();
#pragma unroll
    for (int j = 0; j < 8; j++) {
        int e = tid + 256 * j;
        int rr = e >> 4, c8 = e & 15;
        int gr = row0 + rr;
        if (gr < NN) {
            uint4 v = *(const uint4*)&stage[rr * 136 + c8 * 8];
            *(uint4*)&C[(size_t)gr * HH + col0 + c8 * 8] = v;
        }
    }
}

// ---------------- GCN aggregation (+bias+relu), fp16 in -> fp16 out ------------
__global__ __launch_bounds__(256) void k_gcn_agg_h(const __half* __restrict__ T,
                                                   __half* __restrict__ ah,
                                                   const float* __restrict__ bias) {
    int n = blockIdx.x;
    float din = g_dinv[n];
    int s0 = g_rowstart[n], s1 = g_rowstart[n + 1];
    int f = threadIdx.x;
    float selfw = din * din;
    const __half* rn = T + (size_t)n * HH;
    float a0 = __half2float(rn[f]) * selfw;
    float a1 = __half2float(rn[f + 256]) * selfw;
    float a2 = __half2float(rn[f + 512]) * selfw;
    for (int j = s0; j < s1; j++) {
        int s = g_csrsrc[j];
        float w = g_dinv[s] * din;
        const __half* row = T + (size_t)s * HH;
        a0 += __half2float(row[f]) * w;
        a1 += __half2float(row[f + 256]) * w;
        a2 += __half2float(row[f + 512]) * w;
    }
    size_t base = (size_t)n * HH;
    ah[base + f] = __float2half(fmaxf(a0 + bias[f], 0.f));
    ah[base + f + 256] = __float2half(fmaxf(a1 + bias[f + 256], 0.f));
    ah[base + f + 512] = __float2half(fmaxf(a2 + bias[f + 512], 0.f));
}

// ---------------- GAT alpha (per node, per head dot products), fp16 in --------
__global__ void k_alpha(const __half* __restrict__ Hg, const float* __restrict__ a_src,
                        const float* __restrict__ a_dst) {
    int gwarp = (blockIdx.x * blockDim.x + threadIdx.x) >> 5;
    int lane = threadIdx.x & 31;
    if (gwarp >= NN * NHD) return;
    int n = gwarp / NHD, h = gwarp % NHD;
    const __half* row = Hg + (size_t)n * HH + h * HDD;
    float v0 = __half2float(row[lane]), v1 = __half2float(row[lane + 32]);
    float s = v0 * a_src[h * HDD + lane] + v1 * a_src[h * HDD + lane + 32];
    float d = v0 * a_dst[h * HDD + lane] + v1 * a_dst[h * HDD + lane + 32];
#pragma unroll
    for (int o = 16; o; o >>= 1) {
        s += __shfl_xor_sync(0xFFFFFFFFu, s, o);
        d += __shfl_xor_sync(0xFFFFFFFFu, d, o);
    }
    if (lane == 0) { g_as[gwarp] = s; g_ad[gwarp] = d; }
}

// ---------------- GAT aggregation (per-(edge,head) softmax weights in smem) ----
// mode 1: relu + write fp16 (feeds next GEMM). mode 0: fp32 out, no relu.
#define CH 20
__global__ __launch_bounds__(256) void k_gat_agg(const __half* __restrict__ Hg,
                                                 float* __restrict__ outf,
                                                 __half* __restrict__ ah,
                                                 const float* __restrict__ bias,
                                                 int mode) {
    __shared__ float sm[NHD], ssi[NHD], sself[NHD];
    __shared__ float swgt[CH][NHD];
    int n = blockIdx.x;
    int s0 = g_rowstart[n], s1 = g_rowstart[n + 1];
    int tid = threadIdx.x;

    if (tid < NHD) {
        float adn = g_ad[n * NHD + tid];
        float e_self = lrelu(g_as[n * NHD + tid] + adn);
        float m = e_self;
        for (int j = s0; j < s1; j++) {
            int s = g_csrsrc[j];
            float v = lrelu(g_as[s * NHD + tid] + adn);
            m = fmaxf(m, v);
        }
        float sum = __expf(e_self - m);
        for (int j = s0; j < s1; j++) {
            int s = g_csrsrc[j];
            sum += __expf(lrelu(g_as[s * NHD + tid] + adn) - m);
        }
        float inv = 1.0f / sum;
        sm[tid] = m;
        ssi[tid] = inv;
        sself[tid] = __expf(e_self - m) * inv;
    }
    __syncthreads();

    int h0 = tid >> 6;
    int h1 = (tid + 256) >> 6;
    int h2 = (tid + 512) >> 6;
    const __half* rn = Hg + (size_t)n * HH;
    float acc0 = __half2float(rn[tid]) * sself[h0];
    float acc1 = __half2float(rn[tid + 256]) * sself[h1];
    float acc2v = __half2float(rn[tid + 512]) * sself[h2];

    for (int j0 = s0; j0 < s1; j0 += CH) {
        int cnt = min(CH, s1 - j0);
        if (tid < cnt * NHD) {
            int jj = tid / NHD, h = tid % NHD;
            int s = g_csrsrc[j0 + jj];
            swgt[jj][h] =
                __expf(lrelu(g_as[s * NHD + h] + g_ad[n * NHD + h]) - sm[h]) * ssi[h];
        }
        __syncthreads();
        for (int jj = 0; jj < cnt; jj++) {
            int s = g_csrsrc[j0 + jj];
            const __half* row = Hg + (size_t)s * HH;
            acc0 += __half2float(row[tid]) * swgt[jj][h0];
            acc1 += __half2float(row[tid + 256]) * swgt[jj][h1];
            acc2v += __half2float(row[tid + 512]) * swgt[jj][h2];
        }
        __syncthreads();
    }

    float v0 = acc0 + bias[tid];
    float v1 = acc1 + bias[tid + 256];
    float v2 = acc2v + bias[tid + 512];
    size_t base = (size_t)n * HH;
    if (mode) {
        ah[base + tid] = __float2half(fmaxf(v0, 0.f));
        ah[base + tid + 256] = __float2half(fmaxf(v1, 0.f));
        ah[base + tid + 512] = __float2half(fmaxf(v2, 0.f));
    } else {
        outf[base + tid] = v0;
        outf[base + tid + 256] = v1;
        outf[base + tid + 512] = v2;
    }
}

// ---------------- global mean pool (sorted batch, binary search ranges) --------
__device__ __forceinline__ int lower_bound_batch(const int* b, int key) {
    int lo = 0, hi = NN;
    while (lo < hi) {
        int mid = (lo + hi) >> 1;
        if (b[mid] < key) lo = mid + 1; else hi = mid;
    }
    return lo;
}

__global__ void k_pool(const float* __restrict__ X, const int* __restrict__ batch) {
    int g = blockIdx.x / 12;
    int chunk = blockIdx.x % 12;
    int lo = lower_bound_batch(batch, g);
    int hi = lower_bound_batch(batch, g + 1);
    int f = chunk * 64 + threadIdx.x;
    float s = 0.f;
    for (int i = lo; i < hi; i++) s += X[(size_t)i * HH + f];
    float c = (float)((hi - lo) > 0 ? (hi - lo) : 1);
    g_pool[g * HH + f] = s / c;
}

// ---------------- classifier MLP ----------------
__global__ void k_mlp1(const float* __restrict__ wc1, const float* __restrict__ bc1) {
    __shared__ float sg[HH];
    int g = blockIdx.x;
    for (int i = threadIdx.x; i < HH; i += H2) sg[i] = g_pool[g * HH + i];
    __syncthreads();
    float acc = bc1[threadIdx.x];
    for (int k = 0; k < HH; k++) acc += sg[k] * wc1[k * H2 + threadIdx.x];
    g_zmlp[g * H2 + threadIdx.x] = fmaxf(acc, 0.f);
}

__global__ void k_mlp2(const float* __restrict__ wc2, const float* __restrict__ bc2,
                       float* __restrict__ out) {
    __shared__ float sz[H2];
    int g = blockIdx.x;
    for (int i = threadIdx.x; i < H2; i += 64) sz[i] = g_zmlp[g * H2 + i];
    __syncthreads();
    if (threadIdx.x < NCL) {
        float acc = bc2[threadIdx.x];
        for (int k = 0; k < H2; k++) acc += sz[k] * wc2[k * NCL + threadIdx.x];
        out[g * NCL + threadIdx.x] = acc;
    }
}

// ---------------- launch ----------------
extern "C" void kernel_launch(void* const* d_in, const int* in_sizes, int n_in,
                              void* d_out, int out_size) {
    const float* x    = (const float*)d_in[0];
    const int*   ei   = (const int*)d_in[1];
    const int*   batc = (const int*)d_in[2];
    const float* w1   = (const float*)d_in[3];
    const float* b1   = (const float*)d_in[4];
    const float* w2   = (const float*)d_in[5];
    const float* b2   = (const float*)d_in[6];
    const float* w3   = (const float*)d_in[7];
    const float* b3   = (const float*)d_in[8];
    const float* wg1  = (const float*)d_in[9];
    const float* as1  = (const float*)d_in[10];
    const float* ad1  = (const float*)d_in[11];
    const float* bg1  = (const float*)d_in[12];
    const float* wg2  = (const float*)d_in[13];
    const float* as2  = (const float*)d_in[14];
    const float* ad2  = (const float*)d_in[15];
    const float* bg2  = (const float*)d_in[16];
    const float* wc1  = (const float*)d_in[17];
    const float* bc1  = (const float*)d_in[18];
    const float* wc2  = (const float*)d_in[19];
    const float* bc2  = (const float*)d_in[20];
    float* out = (float*)d_out;

    float* bufA;
    __half *bufB, *Ah, *Wh;
    cudaGetSymbolAddress((void**)&bufA, g_bufA);
    cudaGetSymbolAddress((void**)&bufB, g_bufB);
    cudaGetSymbolAddress((void**)&Ah, g_Ah);
    cudaGetSymbolAddress((void**)&Wh, g_Wh);

    cudaFuncSetAttribute(k_mma_gemm, cudaFuncAttributeMaxDynamicSharedMemorySize,
                         MMA_SMEM);

    dim3 tc_grid((NN + GBM - 1) / GBM, HH / GBN);   // x = row
    int splitW_blocks = (HH * HH) / 256;

    // CSR build
    k_zero_cnt<<<(NN + 255) / 256, 256>>>();
    k_count<<<(EE + 255) / 256, 256>>>(ei);
    k_scan<<<1, 1024>>>();
    k_dinv<<<(NN + 255) / 256, 256>>>();
    k_fill<<<(EE + 255) / 256, 256>>>(ei);

    // GCN layer 1 (fused via linearity): x -> Ah
    k_gcn_l1<<<NN, 256>>>(x, w1, b1, Ah);

    // GCN layer 2
    k_split_w<<<splitW_blocks, 256>>>(w2, Wh);
    k_mma_gemm<<<tc_grid, 256, MMA_SMEM>>>(Ah, Wh, bufB);
    k_gcn_agg_h<<<NN, 256>>>(bufB, Ah, b2);

    // GCN layer 3
    k_split_w<<<splitW_blocks, 256>>>(w3, Wh);
    k_mma_gemm<<<tc_grid, 256, MMA_SMEM>>>(Ah, Wh, bufB);
    k_gcn_agg_h<<<NN, 256>>>(bufB, Ah, b3);

    // GAT layer 1: gemm -> bufB (Hg) ; alpha ; agg -> Ah (relu)
    k_split_w<<<splitW_blocks, 256>>>(wg1, Wh);
    k_mma_gemm<<<tc_grid, 256, MMA_SMEM>>>(Ah, Wh, bufB);
    k_alpha<<<(NN * NHD * 32 + 255) / 256, 256>>>(bufB, as1, ad1);
    k_gat_agg<<<NN, 256>>>(bufB, nullptr, Ah, bg1, 1);

    // GAT layer 2: gemm -> bufB ; alpha ; agg -> bufA (fp32, no relu)
    k_split_w<<<splitW_blocks, 256>>>(wg2, Wh);
    k_mma_gemm<<<tc_grid, 256, MMA_SMEM>>>(Ah, Wh, bufB);
    k_alpha<<<(NN * NHD * 32 + 255) / 256, 256>>>(bufB, as2, ad2);
    k_gat_agg<<<NN, 256>>>(bufB, bufA, nullptr, bg2, 0);

    // pool + MLP
    k_pool<<<NGR * 12, 64>>>(bufA, batc);
    k_mlp1<<<NGR, H2>>>(wc1, bc1);
    k_mlp2<<<NGR, 64>>>(wc2, bc2, out);
}